// round 6
// baseline (speedup 1.0000x reference)
#include <cuda_runtime.h>
#include <math.h>

#define B_ 4
#define S_ 1024
#define E_ 1024
#define H_ 16
#define D_ 64

// ---------------- scratch (alloc-free: __device__ globals, ~64.5 MB) -------
__device__ float g_q[B_*H_*S_*D_];          // 16 MB  [b,h,s,d]
__device__ float g_k[B_*H_*S_*D_];          // 16 MB
__device__ float g_v[B_*H_*S_*D_];          // 16 MB
__device__ float g_ctx[B_*S_*E_];           // 16 MB  [b,s,h*D+d]
__device__ float g_m[B_*H_*S_];             // row max   (post-bias scores)
__device__ float g_l[B_*H_*S_];             // row sumexp
__device__ float g_maskbias[B_*S_];         // additive 0 / -inf

// ---------------- tf32 helpers ----------------
__device__ __forceinline__ unsigned f2tf(float x) {
    unsigned u; asm("cvt.rna.tf32.f32 %0, %1;" : "=r"(u) : "f"(x)); return u;
}
__device__ __forceinline__ float f2tff(float x) { return __uint_as_float(f2tf(x)); }

// D += A(16x8, row) * B(8x8, col);  c[4] fp32, a[4]/b[2] tf32 bits
__device__ __forceinline__ void mma_tf32(float* c, const unsigned* a, const unsigned* b) {
    asm volatile(
        "mma.sync.aligned.m16n8k8.row.col.f32.tf32.tf32.f32 "
        "{%0,%1,%2,%3}, {%4,%5,%6,%7}, {%8,%9}, {%0,%1,%2,%3};"
        : "+f"(c[0]), "+f"(c[1]), "+f"(c[2]), "+f"(c[3])
        : "r"(a[0]), "r"(a[1]), "r"(a[2]), "r"(a[3]), "r"(b[0]), "r"(b[1]));
}

// ---------------- mask dtype detection + expansion ----------------
__global__ void mask_kernel(const void* __restrict__ mask_raw) {
    __shared__ int s_int, s_flt;
    int t = threadIdx.x;                        // 1024 threads
    if (t == 0) { s_int = 1; s_flt = 1; }
    __syncthreads();
    const unsigned int* w = (const unsigned int*)mask_raw;
    unsigned int v = w[t];
    if (!(v == 0u || v == 1u))           atomicAnd(&s_int, 0);
    if (!(v == 0u || v == 0x3f800000u))  atomicAnd(&s_flt, 0);
    __syncthreads();
    int mode = s_int ? 0 : (s_flt ? 1 : 2);
    for (int i = t; i < B_*S_; i += 1024) {
        bool keep;
        if (mode == 0)      keep = ((const int*)mask_raw)[i] != 0;
        else if (mode == 1) keep = ((const float*)mask_raw)[i] != 0.0f;
        else                keep = ((const unsigned char*)mask_raw)[i] != 0;
        g_maskbias[i] = keep ? 0.0f : -INFINITY;
    }
}

// ---------------- K1: QKV projection (tf32 mma) -----------------------------
__global__ __launch_bounds__(256) void qkv_gemm(
    const float* __restrict__ qin, const float* __restrict__ kin,
    const float* __restrict__ vin, const float* __restrict__ W,
    const float* __restrict__ bias)
{
    int z = blockIdx.z;
    const float* A  = (z == 0) ? qin : (z == 1) ? kin : vin;
    const float* Wz = W + z * E_ * E_;
    const float* bz = bias + z * E_;
    float* outp = (z == 0) ? g_q : (z == 1) ? g_k : g_v;

    __shared__ float As[128][36];
    __shared__ float Ws[64][36];
    int t = threadIdx.x, w = t >> 5, lane = t & 31, g = lane >> 2, tig = lane & 3;
    int wm = (w & 3) * 32, wn = (w >> 2) * 32;
    int m0 = blockIdx.y * 128, n0 = blockIdx.x * 64;

    float acc[2][4][4] = {};
    int ar = t >> 3, ac = (t & 7) * 4;
    int wr = t >> 2, wc = (t & 3) * 8;

    for (int k0 = 0; k0 < E_; k0 += 32) {
        #pragma unroll
        for (int p = 0; p < 4; p++) {
            float4 v = *(const float4*)(A + (size_t)(m0 + ar + p*32) * E_ + k0 + ac);
            As[ar + p*32][ac+0] = f2tff(v.x); As[ar + p*32][ac+1] = f2tff(v.y);
            As[ar + p*32][ac+2] = f2tff(v.z); As[ar + p*32][ac+3] = f2tff(v.w);
        }
        {
            float4 v0 = *(const float4*)(Wz + (size_t)(n0 + wr) * E_ + k0 + wc);
            float4 v1 = *(const float4*)(Wz + (size_t)(n0 + wr) * E_ + k0 + wc + 4);
            Ws[wr][wc+0] = f2tff(v0.x); Ws[wr][wc+1] = f2tff(v0.y);
            Ws[wr][wc+2] = f2tff(v0.z); Ws[wr][wc+3] = f2tff(v0.w);
            Ws[wr][wc+4] = f2tff(v1.x); Ws[wr][wc+5] = f2tff(v1.y);
            Ws[wr][wc+6] = f2tff(v1.z); Ws[wr][wc+7] = f2tff(v1.w);
        }
        __syncthreads();
        #pragma unroll
        for (int ks = 0; ks < 4; ks++) {
            unsigned a[2][4], bf[4][2];
            #pragma unroll
            for (int mt = 0; mt < 2; mt++) {
                int r = wm + mt*16 + g, k = ks*8 + tig;
                a[mt][0] = __float_as_uint(As[r  ][k  ]);
                a[mt][1] = __float_as_uint(As[r+8][k  ]);
                a[mt][2] = __float_as_uint(As[r  ][k+4]);
                a[mt][3] = __float_as_uint(As[r+8][k+4]);
            }
            #pragma unroll
            for (int nt = 0; nt < 4; nt++) {
                int n = wn + nt*8 + g, k = ks*8 + tig;
                bf[nt][0] = __float_as_uint(Ws[n][k  ]);
                bf[nt][1] = __float_as_uint(Ws[n][k+4]);
            }
            #pragma unroll
            for (int mt = 0; mt < 2; mt++)
                #pragma unroll
                for (int nt = 0; nt < 4; nt++)
                    mma_tf32(acc[mt][nt], a[mt], bf[nt]);
        }
        __syncthreads();
    }
    #pragma unroll
    for (int mt = 0; mt < 2; mt++) {
        int m_ = m0 + wm + mt*16 + g;
        int bb = m_ >> 10, s0 = m_ & 1023;
        #pragma unroll
        for (int nt = 0; nt < 4; nt++) {
            int n_ = n0 + wn + nt*8 + tig*2;
            int h = n_ >> 6, d = n_ & 63;
            float bx = bz[n_], by = bz[n_+1];
            *(float2*)&outp[(((bb*H_ + h)*S_ + s0    )*D_) + d] =
                make_float2(acc[mt][nt][0] + bx, acc[mt][nt][1] + by);
            *(float2*)&outp[(((bb*H_ + h)*S_ + s0 + 8)*D_) + d] =
                make_float2(acc[mt][nt][2] + bx, acc[mt][nt][3] + by);
        }
    }
}

// ---------------- K2: fused flash attention (tf32 mma), 4 warps -------------
// q-tile 64, k-tile 64; Q fragments register-resident; K smem reused for P.
__global__ __launch_bounds__(128) void flash_kernel() {
    int bh = blockIdx.y; int b = bh >> 4, h = bh & 15;
    int m0 = blockIdx.x * 64;
    const float* Q  = g_q + (size_t)bh * S_ * D_;
    const float* Kp = g_k + (size_t)bh * S_ * D_;
    const float* V  = g_v + (size_t)bh * S_ * D_;
    const float* mb = g_maskbias + b * S_;

    __shared__ float Ks[64][68];   // K tile; reused as P tile after S-mma
    __shared__ float Vs[64][68];

    int t = threadIdx.x, w = t >> 5, lane = t & 31, g = lane >> 2, tig = lane & 3;
    int wm = w * 16;
    int r_lo = m0 + wm + g, r_hi = r_lo + 8;

    // stage Q tile through Ks, hoist A-fragments into registers
    {
        int r = t >> 1, c0 = (t & 1) * 32;
        #pragma unroll
        for (int j = 0; j < 8; j++) {
            float4 v = *(const float4*)(Q + (size_t)(m0 + r) * D_ + c0 + j*4);
            Ks[r][c0+j*4+0] = f2tff(v.x); Ks[r][c0+j*4+1] = f2tff(v.y);
            Ks[r][c0+j*4+2] = f2tff(v.z); Ks[r][c0+j*4+3] = f2tff(v.w);
        }
    }
    __syncthreads();
    unsigned aq[8][4];
    #pragma unroll
    for (int ks = 0; ks < 8; ks++) {
        int k = ks*8 + tig;
        aq[ks][0] = __float_as_uint(Ks[wm+g  ][k  ]);
        aq[ks][1] = __float_as_uint(Ks[wm+g+8][k  ]);
        aq[ks][2] = __float_as_uint(Ks[wm+g  ][k+4]);
        aq[ks][3] = __float_as_uint(Ks[wm+g+8][k+4]);
    }

    float acc[8][4] = {};
    float mlo = -1e30f, mhi = -1e30f, llo = 0.0f, lhi = 0.0f;

    for (int kt = 0; kt < 16; kt++) {
        __syncthreads();        // prev iter's Ps/Vs readers done (Q frags loaded, iter 0)
        {   // K,V tiles 64x64 -> smem (tf32)
            int kr = t >> 1, c0 = (t & 1) * 32;
            #pragma unroll
            for (int j = 0; j < 8; j++) {
                float4 kv = *(const float4*)(Kp + (size_t)(kt*64 + kr) * D_ + c0 + j*4);
                Ks[kr][c0+j*4+0] = f2tff(kv.x); Ks[kr][c0+j*4+1] = f2tff(kv.y);
                Ks[kr][c0+j*4+2] = f2tff(kv.z); Ks[kr][c0+j*4+3] = f2tff(kv.w);
                float4 vv = *(const float4*)(V + (size_t)(kt*64 + kr) * D_ + c0 + j*4);
                Vs[kr][c0+j*4+0] = f2tff(vv.x); Vs[kr][c0+j*4+1] = f2tff(vv.y);
                Vs[kr][c0+j*4+2] = f2tff(vv.z); Vs[kr][c0+j*4+3] = f2tff(vv.w);
            }
        }
        __syncthreads();

        // S(16x64 per warp) = Q . K^T
        float s[8][4] = {};
        #pragma unroll
        for (int ks = 0; ks < 8; ks++) {
            int k = ks*8 + tig;
            #pragma unroll
            for (int nt = 0; nt < 8; nt++) {
                unsigned bf[2];
                bf[0] = __float_as_uint(Ks[nt*8+g][k  ]);
                bf[1] = __float_as_uint(Ks[nt*8+g][k+4]);
                mma_tf32(s[nt], aq[ks], bf);
            }
        }

        // scale + rel bias + mask, online softmax over 64 cols
        float rml = -1e30f, rmh = -1e30f;
        #pragma unroll
        for (int nt = 0; nt < 8; nt++) {
            int c = kt*64 + nt*8 + tig*2;
            float mb0 = mb[c], mb1 = mb[c+1];
            s[nt][0] = s[nt][0]*0.125f + (float)(r_lo - c    ) + mb0;
            s[nt][1] = s[nt][1]*0.125f + (float)(r_lo - c - 1) + mb1;
            s[nt][2] = s[nt][2]*0.125f + (float)(r_hi - c    ) + mb0;
            s[nt][3] = s[nt][3]*0.125f + (float)(r_hi - c - 1) + mb1;
            rml = fmaxf(rml, fmaxf(s[nt][0], s[nt][1]));
            rmh = fmaxf(rmh, fmaxf(s[nt][2], s[nt][3]));
        }
        rml = fmaxf(rml, __shfl_xor_sync(0xffffffffu, rml, 1));
        rml = fmaxf(rml, __shfl_xor_sync(0xffffffffu, rml, 2));
        rmh = fmaxf(rmh, __shfl_xor_sync(0xffffffffu, rmh, 1));
        rmh = fmaxf(rmh, __shfl_xor_sync(0xffffffffu, rmh, 2));

        float mnl = fmaxf(mlo, rml), mnh = fmaxf(mhi, rmh);
        float sfl = __expf(mlo - mnl), sfh = __expf(mhi - mnh);
        float p[8][4];
        float rsl = 0.0f, rsh = 0.0f;
        #pragma unroll
        for (int nt = 0; nt < 8; nt++) {
            p[nt][0] = __expf(s[nt][0] - mnl); p[nt][1] = __expf(s[nt][1] - mnl);
            p[nt][2] = __expf(s[nt][2] - mnh); p[nt][3] = __expf(s[nt][3] - mnh);
            rsl += p[nt][0] + p[nt][1]; rsh += p[nt][2] + p[nt][3];
        }
        rsl += __shfl_xor_sync(0xffffffffu, rsl, 1);
        rsl += __shfl_xor_sync(0xffffffffu, rsl, 2);
        rsh += __shfl_xor_sync(0xffffffffu, rsh, 1);
        rsh += __shfl_xor_sync(0xffffffffu, rsh, 2);
        llo = llo*sfl + rsl; lhi = lhi*sfh + rsh;
        mlo = mnl; mhi = mnh;
        #pragma unroll
        for (int nt = 0; nt < 8; nt++) {
            acc[nt][0] *= sfl; acc[nt][1] *= sfl;
            acc[nt][2] *= sfh; acc[nt][3] *= sfh;
        }

        __syncthreads();        // all warps done reading Ks -> safe to overwrite with P
        #pragma unroll
        for (int nt = 0; nt < 8; nt++) {
            int c = nt*8 + tig*2;
            Ks[wm+g  ][c] = f2tff(p[nt][0]); Ks[wm+g  ][c+1] = f2tff(p[nt][1]);
            Ks[wm+g+8][c] = f2tff(p[nt][2]); Ks[wm+g+8][c+1] = f2tff(p[nt][3]);
        }
        __syncwarp();           // P rows are warp-local

        // acc(16x64) += P(16x64) . V(64x64)
        #pragma unroll
        for (int ks = 0; ks < 8; ks++) {
            int k = ks*8 + tig;
            unsigned a[4];
            a[0] = __float_as_uint(Ks[wm+g  ][k  ]);
            a[1] = __float_as_uint(Ks[wm+g+8][k  ]);
            a[2] = __float_as_uint(Ks[wm+g  ][k+4]);
            a[3] = __float_as_uint(Ks[wm+g+8][k+4]);
            #pragma unroll
            for (int nt = 0; nt < 8; nt++) {
                unsigned bf[2];
                bf[0] = __float_as_uint(Vs[k  ][nt*8+g]);
                bf[1] = __float_as_uint(Vs[k+4][nt*8+g]);
                mma_tf32(acc[nt], a, bf);
            }
        }
    }

    float il = 1.0f / llo, ih = 1.0f / lhi;
    float* clo = &g_ctx[((size_t)(b*S_ + r_lo))*E_ + h*D_];
    float* chi = &g_ctx[((size_t)(b*S_ + r_hi))*E_ + h*D_];
    #pragma unroll
    for (int nt = 0; nt < 8; nt++) {
        int d = nt*8 + tig*2;
        *(float2*)&clo[d] = make_float2(acc[nt][0]*il, acc[nt][1]*il);
        *(float2*)&chi[d] = make_float2(acc[nt][2]*ih, acc[nt][3]*ih);
    }
    if (tig == 0) {
        g_m[(size_t)bh*S_ + r_lo] = mlo; g_l[(size_t)bh*S_ + r_lo] = llo;
        g_m[(size_t)bh*S_ + r_hi] = mhi; g_l[(size_t)bh*S_ + r_hi] = lhi;
    }
}

// ---------------- K3: attn mean over heads (tf32 mma recompute), 8 warps ----
// 64x64 tile, warp w covers q-rows (w&3)*16 x k-cols (w>>2)*32.
__global__ __launch_bounds__(256) void attnmean_kernel(float* __restrict__ out_attn) {
    int kt = blockIdx.x, m0 = blockIdx.y * 64, b = blockIdx.z;
    __shared__ float Qs[64][68];
    __shared__ float Ks[64][68];
    int t = threadIdx.x, w = t >> 5, lane = t & 31, g = lane >> 2, tig = lane & 3;
    int qm = (w & 3) * 16, kn = (w >> 2) * 32;
    int r_lo = m0 + qm + g, r_hi = r_lo + 8;
    const float* mb = g_maskbias + b * S_;

    float acc[4][4] = {};
    for (int h = 0; h < H_; h++) {
        int bh = b*H_ + h;
        const float* Q  = g_q + (size_t)bh * S_ * D_;
        const float* Kp = g_k + (size_t)bh * S_ * D_ + (size_t)kt * 64 * D_;
        __syncthreads();
        {
            int r = t >> 2, c0 = (t & 3) * 16;
            #pragma unroll
            for (int j = 0; j < 4; j++) {
                float4 qv = *(const float4*)(Q + (size_t)(m0 + r) * D_ + c0 + j*4);
                Qs[r][c0+j*4+0] = f2tff(qv.x); Qs[r][c0+j*4+1] = f2tff(qv.y);
                Qs[r][c0+j*4+2] = f2tff(qv.z); Qs[r][c0+j*4+3] = f2tff(qv.w);
                float4 kv = *(const float4*)(Kp + (size_t)r * D_ + c0 + j*4);
                Ks[r][c0+j*4+0] = f2tff(kv.x); Ks[r][c0+j*4+1] = f2tff(kv.y);
                Ks[r][c0+j*4+2] = f2tff(kv.z); Ks[r][c0+j*4+3] = f2tff(kv.w);
            }
        }
        __syncthreads();

        float s[4][4] = {};
        #pragma unroll
        for (int ks = 0; ks < 8; ks++) {
            int k = ks*8 + tig;
            unsigned a[4];
            a[0] = __float_as_uint(Qs[qm+g  ][k  ]);
            a[1] = __float_as_uint(Qs[qm+g+8][k  ]);
            a[2] = __float_as_uint(Qs[qm+g  ][k+4]);
            a[3] = __float_as_uint(Qs[qm+g+8][k+4]);
            #pragma unroll
            for (int nt = 0; nt < 4; nt++) {
                unsigned bf[2];
                bf[0] = __float_as_uint(Ks[kn+nt*8+g][k  ]);
                bf[1] = __float_as_uint(Ks[kn+nt*8+g][k+4]);
                mma_tf32(s[nt], a, bf);
            }
        }

        float ml = g_m[(size_t)bh*S_ + r_lo], il = 1.0f / g_l[(size_t)bh*S_ + r_lo];
        float mh = g_m[(size_t)bh*S_ + r_hi], ih = 1.0f / g_l[(size_t)bh*S_ + r_hi];
        #pragma unroll
        for (int nt = 0; nt < 4; nt++) {
            int c = kt*64 + kn + nt*8 + tig*2;
            float mb0 = mb[c], mb1 = mb[c+1];
            acc[nt][0] += __expf(s[nt][0]*0.125f + (float)(r_lo - c    ) + mb0 - ml) * il;
            acc[nt][1] += __expf(s[nt][1]*0.125f + (float)(r_lo - c - 1) + mb1 - ml) * il;
            acc[nt][2] += __expf(s[nt][2]*0.125f + (float)(r_hi - c    ) + mb0 - mh) * ih;
            acc[nt][3] += __expf(s[nt][3]*0.125f + (float)(r_hi - c - 1) + mb1 - mh) * ih;
        }
    }
    float* olo = &out_attn[((size_t)(b*S_ + r_lo))*S_ + kt*64 + kn];
    float* ohi = &out_attn[((size_t)(b*S_ + r_hi))*S_ + kt*64 + kn];
    #pragma unroll
    for (int nt = 0; nt < 4; nt++) {
        int c = nt*8 + tig*2;
        *(float2*)&olo[c] = make_float2(acc[nt][0]*0.0625f, acc[nt][1]*0.0625f);
        *(float2*)&ohi[c] = make_float2(acc[nt][2]*0.0625f, acc[nt][3]*0.0625f);
    }
}

// ---------------- K4: out = ctx @ Wo^T + bo (tf32 mma) ----------------------
__global__ __launch_bounds__(256) void out_gemm(
    const float* __restrict__ W, const float* __restrict__ bias,
    float* __restrict__ out)
{
    __shared__ float As[128][36];
    __shared__ float Ws[64][36];
    int t = threadIdx.x, w = t >> 5, lane = t & 31, g = lane >> 2, tig = lane & 3;
    int wm = (w & 3) * 32, wn = (w >> 2) * 32;
    int m0 = blockIdx.y * 128, n0 = blockIdx.x * 64;

    float acc[2][4][4] = {};
    int ar = t >> 3, ac = (t & 7) * 4;
    int wr = t >> 2, wc = (t & 3) * 8;

    for (int k0 = 0; k0 < E_; k0 += 32) {
        #pragma unroll
        for (int p = 0; p < 4; p++) {
            float4 v = *(const float4*)(g_ctx + (size_t)(m0 + ar + p*32) * E_ + k0 + ac);
            As[ar + p*32][ac+0] = f2tff(v.x); As[ar + p*32][ac+1] = f2tff(v.y);
            As[ar + p*32][ac+2] = f2tff(v.z); As[ar + p*32][ac+3] = f2tff(v.w);
        }
        {
            float4 v0 = *(const float4*)(W + (size_t)(n0 + wr) * E_ + k0 + wc);
            float4 v1 = *(const float4*)(W + (size_t)(n0 + wr) * E_ + k0 + wc + 4);
            Ws[wr][wc+0] = f2tff(v0.x); Ws[wr][wc+1] = f2tff(v0.y);
            Ws[wr][wc+2] = f2tff(v0.z); Ws[wr][wc+3] = f2tff(v0.w);
            Ws[wr][wc+4] = f2tff(v1.x); Ws[wr][wc+5] = f2tff(v1.y);
            Ws[wr][wc+6] = f2tff(v1.z); Ws[wr][wc+7] = f2tff(v1.w);
        }
        __syncthreads();
        #pragma unroll
        for (int ks = 0; ks < 4; ks++) {
            unsigned a[2][4], bf[4][2];
            #pragma unroll
            for (int mt = 0; mt < 2; mt++) {
                int r = wm + mt*16 + g, k = ks*8 + tig;
                a[mt][0] = __float_as_uint(As[r  ][k  ]);
                a[mt][1] = __float_as_uint(As[r+8][k  ]);
                a[mt][2] = __float_as_uint(As[r  ][k+4]);
                a[mt][3] = __float_as_uint(As[r+8][k+4]);
            }
            #pragma unroll
            for (int nt = 0; nt < 4; nt++) {
                int n = wn + nt*8 + g, k = ks*8 + tig;
                bf[nt][0] = __float_as_uint(Ws[n][k  ]);
                bf[nt][1] = __float_as_uint(Ws[n][k+4]);
            }
            #pragma unroll
            for (int mt = 0; mt < 2; mt++)
                #pragma unroll
                for (int nt = 0; nt < 4; nt++)
                    mma_tf32(acc[mt][nt], a[mt], bf[nt]);
        }
        __syncthreads();
    }
    #pragma unroll
    for (int mt = 0; mt < 2; mt++) {
        int m_ = m0 + wm + mt*16 + g;
        #pragma unroll
        for (int nt = 0; nt < 4; nt++) {
            int n_ = n0 + wn + nt*8 + tig*2;
            float bx = bias[n_], by = bias[n_+1];
            *(float2*)&out[(size_t)m_ * E_ + n_] =
                make_float2(acc[mt][nt][0] + bx, acc[mt][nt][1] + by);
            *(float2*)&out[(size_t)(m_+8) * E_ + n_] =
                make_float2(acc[mt][nt][2] + bx, acc[mt][nt][3] + by);
        }
    }
}

// ---------------- launch ----------------------------------------------------
extern "C" void kernel_launch(void* const* d_in, const int* in_sizes, int n_in,
                              void* d_out, int out_size)
{
    const float* query = (const float*)d_in[0];
    const float* key   = (const float*)d_in[1];
    const float* value = (const float*)d_in[2];
    const void*  mask  = d_in[3];
    const float* win   = (const float*)d_in[4];
    const float* bin   = (const float*)d_in[5];
    const float* wout  = (const float*)d_in[6];
    const float* bout  = (const float*)d_in[7];

    float* out      = (float*)d_out;                      // [4,1024,1024] output
    float* out_attn = out + (size_t)B_ * S_ * E_;         // [4,1024,1024] attn mean

    mask_kernel<<<1, 1024>>>(mask);
    qkv_gemm<<<dim3(16, 32, 3), 256>>>(query, key, value, win, bin);
    flash_kernel<<<dim3(16, 64), 128>>>();
    attnmean_kernel<<<dim3(16, 16, 4), 256>>>(out_attn);
    out_gemm<<<dim3(16, 32), 256>>>(wout, bout, out);
}

// round 7
// speedup vs baseline: 1.3728x; 1.3728x over previous
#include <cuda_runtime.h>
#include <cuda_fp16.h>
#include <math.h>

#define B_ 4
#define S_ 1024
#define E_ 1024
#define H_ 16
#define D_ 64

// ---------------- scratch (alloc-free: __device__ globals, ~64.5 MB) -------
__device__ float g_q[B_*H_*S_*D_];          // 16 MB  [b,h,s,d]
__device__ float g_k[B_*H_*S_*D_];          // 16 MB
__device__ float g_v[B_*H_*S_*D_];          // 16 MB
__device__ float g_ctx[B_*S_*E_];           // 16 MB  [b,s,h*D+d]
__device__ float g_m[B_*H_*S_];             // row max   (post-bias scores)
__device__ float g_l[B_*H_*S_];             // row sumexp
__device__ float g_maskbias[B_*S_];         // additive 0 / -inf

// ---------------- fp16 helpers ----------------
__device__ __forceinline__ unsigned h2(float a, float b) {
    __half2 h = __floats2half2_rn(a, b);
    return *reinterpret_cast<unsigned*>(&h);
}

// D += A(16x16, row) * B(16x8, col); c[4] fp32, a[4]/b[2] = half2 regs
__device__ __forceinline__ void mma_f16(float* c, const unsigned* a, const unsigned* b) {
    asm volatile(
        "mma.sync.aligned.m16n8k16.row.col.f32.f16.f16.f32 "
        "{%0,%1,%2,%3}, {%4,%5,%6,%7}, {%8,%9}, {%0,%1,%2,%3};"
        : "+f"(c[0]), "+f"(c[1]), "+f"(c[2]), "+f"(c[3])
        : "r"(a[0]), "r"(a[1]), "r"(a[2]), "r"(a[3]), "r"(b[0]), "r"(b[1]));
}

// ---------------- mask dtype detection + expansion ----------------
__global__ void mask_kernel(const void* __restrict__ mask_raw) {
    __shared__ int s_int, s_flt;
    int t = threadIdx.x;                        // 1024 threads
    if (t == 0) { s_int = 1; s_flt = 1; }
    __syncthreads();
    const unsigned int* w = (const unsigned int*)mask_raw;
    unsigned int v = w[t];
    if (!(v == 0u || v == 1u))           atomicAnd(&s_int, 0);
    if (!(v == 0u || v == 0x3f800000u))  atomicAnd(&s_flt, 0);
    __syncthreads();
    int mode = s_int ? 0 : (s_flt ? 1 : 2);
    for (int i = t; i < B_*S_; i += 1024) {
        bool keep;
        if (mode == 0)      keep = ((const int*)mask_raw)[i] != 0;
        else if (mode == 1) keep = ((const float*)mask_raw)[i] != 0.0f;
        else                keep = ((const unsigned char*)mask_raw)[i] != 0;
        g_maskbias[i] = keep ? 0.0f : -INFINITY;
    }
}

// ---------------- K1: QKV projection (fp16 mma) -----------------------------
// BM=128 BN=64 BK=32; 8 warps (4m x 2n). Smem tiles half2, stride 20 words.
__global__ __launch_bounds__(256) void qkv_gemm(
    const float* __restrict__ qin, const float* __restrict__ kin,
    const float* __restrict__ vin, const float* __restrict__ W,
    const float* __restrict__ bias)
{
    int z = blockIdx.z;
    const float* A  = (z == 0) ? qin : (z == 1) ? kin : vin;
    const float* Wz = W + z * E_ * E_;
    const float* bz = bias + z * E_;
    float* outp = (z == 0) ? g_q : (z == 1) ? g_k : g_v;

    __shared__ unsigned As[128][20];   // 128 rows x 16 half2 (+4 pad)
    __shared__ unsigned Ws[64][20];
    int t = threadIdx.x, w = t >> 5, lane = t & 31, g = lane >> 2, tig = lane & 3;
    int wm = (w & 3) * 32, wn = (w >> 2) * 32;
    int m0 = blockIdx.y * 128, n0 = blockIdx.x * 64;

    float acc[2][4][4] = {};
    int ar = t >> 3, ac2 = (t & 7) * 2;     // A: 32 rows/pass, half2 col pair
    int wr = t >> 2, wc2 = (t & 3) * 4;     // W: 64 rows, 4 half2 each

    for (int k0 = 0; k0 < E_; k0 += 32) {
        #pragma unroll
        for (int p = 0; p < 4; p++) {
            float4 v = *(const float4*)(A + (size_t)(m0 + ar + p*32) * E_ + k0 + ac2*2);
            As[ar + p*32][ac2]   = h2(v.x, v.y);
            As[ar + p*32][ac2+1] = h2(v.z, v.w);
        }
        {
            float4 v0 = *(const float4*)(Wz + (size_t)(n0 + wr) * E_ + k0 + wc2*2);
            float4 v1 = *(const float4*)(Wz + (size_t)(n0 + wr) * E_ + k0 + wc2*2 + 4);
            Ws[wr][wc2]   = h2(v0.x, v0.y); Ws[wr][wc2+1] = h2(v0.z, v0.w);
            Ws[wr][wc2+2] = h2(v1.x, v1.y); Ws[wr][wc2+3] = h2(v1.z, v1.w);
        }
        __syncthreads();
        #pragma unroll
        for (int ks = 0; ks < 2; ks++) {
            int kp = ks*8 + tig;
            unsigned a[2][4], bf[4][2];
            #pragma unroll
            for (int mt = 0; mt < 2; mt++) {
                int r = wm + mt*16 + g;
                a[mt][0] = As[r  ][kp];   a[mt][1] = As[r+8][kp];
                a[mt][2] = As[r  ][kp+4]; a[mt][3] = As[r+8][kp+4];
            }
            #pragma unroll
            for (int nt = 0; nt < 4; nt++) {
                int n = wn + nt*8 + g;
                bf[nt][0] = Ws[n][kp]; bf[nt][1] = Ws[n][kp+4];
            }
            #pragma unroll
            for (int mt = 0; mt < 2; mt++)
                #pragma unroll
                for (int nt = 0; nt < 4; nt++)
                    mma_f16(acc[mt][nt], a[mt], bf[nt]);
        }
        __syncthreads();
    }
    #pragma unroll
    for (int mt = 0; mt < 2; mt++) {
        int m_ = m0 + wm + mt*16 + g;
        int bb = m_ >> 10, s0 = m_ & 1023;
        #pragma unroll
        for (int nt = 0; nt < 4; nt++) {
            int n_ = n0 + wn + nt*8 + tig*2;
            int h = n_ >> 6, d = n_ & 63;
            float bx = bz[n_], by = bz[n_+1];
            *(float2*)&outp[(((bb*H_ + h)*S_ + s0    )*D_) + d] =
                make_float2(acc[mt][nt][0] + bx, acc[mt][nt][1] + by);
            *(float2*)&outp[(((bb*H_ + h)*S_ + s0 + 8)*D_) + d] =
                make_float2(acc[mt][nt][2] + bx, acc[mt][nt][3] + by);
        }
    }
}

// ---------------- K2: fused flash attention (fp16 mma), 4 warps -------------
// q-tile 64, k-tile 64; Q fragments register-resident; K smem reused for P.
__global__ __launch_bounds__(128) void flash_kernel() {
    int bh = blockIdx.y; int b = bh >> 4, h = bh & 15;
    int m0 = blockIdx.x * 64;
    const float* Q  = g_q + (size_t)bh * S_ * D_;
    const float* Kp = g_k + (size_t)bh * S_ * D_;
    const float* V  = g_v + (size_t)bh * S_ * D_;
    const float* mb = g_maskbias + b * S_;

    __shared__ unsigned Ks[64][36];   // K tile [key][k-pair]; reused as P tile
    __shared__ unsigned Vt[64][36];   // V transposed [d][k-pair]

    int t = threadIdx.x, w = t >> 5, lane = t & 31, g = lane >> 2, tig = lane & 3;
    int wm = w * 16;
    int r_lo = m0 + wm + g, r_hi = r_lo + 8;

    // stage Q through Ks, hoist A-fragments (half2) to registers
    {
        int r = t >> 1, c0 = (t & 1) * 32;
        #pragma unroll
        for (int j = 0; j < 8; j++) {
            float4 v = *(const float4*)(Q + (size_t)(m0 + r) * D_ + c0 + j*4);
            Ks[r][(c0 + j*4)/2]     = h2(v.x, v.y);
            Ks[r][(c0 + j*4)/2 + 1] = h2(v.z, v.w);
        }
    }
    __syncthreads();
    unsigned aq[4][4];
    #pragma unroll
    for (int ks = 0; ks < 4; ks++) {
        int kp = ks*8 + tig;
        aq[ks][0] = Ks[wm+g  ][kp];   aq[ks][1] = Ks[wm+g+8][kp];
        aq[ks][2] = Ks[wm+g  ][kp+4]; aq[ks][3] = Ks[wm+g+8][kp+4];
    }

    float acc[8][4] = {};
    float mlo = -1e30f, mhi = -1e30f, llo = 0.0f, lhi = 0.0f;
    __half* vth = reinterpret_cast<__half*>(&Vt[0][0]);

    for (int kt = 0; kt < 16; kt++) {
        __syncthreads();        // prior readers of Ks/Vt done (incl. aq loads, iter 0)
        {   // K row-major half2; V transposed halves
            int kr = t >> 1, c0 = (t & 1) * 32;
            #pragma unroll
            for (int j = 0; j < 8; j++) {
                float4 kv = *(const float4*)(Kp + (size_t)(kt*64 + kr) * D_ + c0 + j*4);
                Ks[kr][(c0 + j*4)/2]     = h2(kv.x, kv.y);
                Ks[kr][(c0 + j*4)/2 + 1] = h2(kv.z, kv.w);
                float4 vv = *(const float4*)(V + (size_t)(kt*64 + kr) * D_ + c0 + j*4);
                vth[(c0 + j*4 + 0)*72 + kr] = __float2half_rn(vv.x);
                vth[(c0 + j*4 + 1)*72 + kr] = __float2half_rn(vv.y);
                vth[(c0 + j*4 + 2)*72 + kr] = __float2half_rn(vv.z);
                vth[(c0 + j*4 + 3)*72 + kr] = __float2half_rn(vv.w);
            }
        }
        __syncthreads();

        // S(16x64 per warp) = Q . K^T
        float s[8][4] = {};
        #pragma unroll
        for (int ks = 0; ks < 4; ks++) {
            int kp = ks*8 + tig;
            #pragma unroll
            for (int nt = 0; nt < 8; nt++) {
                unsigned bf[2] = { Ks[nt*8+g][kp], Ks[nt*8+g][kp+4] };
                mma_f16(s[nt], aq[ks], bf);
            }
        }

        // scale + rel bias + mask, online softmax over 64 cols
        float rml = -1e30f, rmh = -1e30f;
        #pragma unroll
        for (int nt = 0; nt < 8; nt++) {
            int c = kt*64 + nt*8 + tig*2;
            float mb0 = mb[c], mb1 = mb[c+1];
            s[nt][0] = s[nt][0]*0.125f + (float)(r_lo - c    ) + mb0;
            s[nt][1] = s[nt][1]*0.125f + (float)(r_lo - c - 1) + mb1;
            s[nt][2] = s[nt][2]*0.125f + (float)(r_hi - c    ) + mb0;
            s[nt][3] = s[nt][3]*0.125f + (float)(r_hi - c - 1) + mb1;
            rml = fmaxf(rml, fmaxf(s[nt][0], s[nt][1]));
            rmh = fmaxf(rmh, fmaxf(s[nt][2], s[nt][3]));
        }
        rml = fmaxf(rml, __shfl_xor_sync(0xffffffffu, rml, 1));
        rml = fmaxf(rml, __shfl_xor_sync(0xffffffffu, rml, 2));
        rmh = fmaxf(rmh, __shfl_xor_sync(0xffffffffu, rmh, 1));
        rmh = fmaxf(rmh, __shfl_xor_sync(0xffffffffu, rmh, 2));

        float mnl = fmaxf(mlo, rml), mnh = fmaxf(mhi, rmh);
        float sfl = __expf(mlo - mnl), sfh = __expf(mhi - mnh);
        float rsl = 0.0f, rsh = 0.0f;
        #pragma unroll
        for (int nt = 0; nt < 8; nt++) {   // p overwrites s (register reuse)
            s[nt][0] = __expf(s[nt][0] - mnl); s[nt][1] = __expf(s[nt][1] - mnl);
            s[nt][2] = __expf(s[nt][2] - mnh); s[nt][3] = __expf(s[nt][3] - mnh);
            rsl += s[nt][0] + s[nt][1]; rsh += s[nt][2] + s[nt][3];
        }
        rsl += __shfl_xor_sync(0xffffffffu, rsl, 1);
        rsl += __shfl_xor_sync(0xffffffffu, rsl, 2);
        rsh += __shfl_xor_sync(0xffffffffu, rsh, 1);
        rsh += __shfl_xor_sync(0xffffffffu, rsh, 2);
        llo = llo*sfl + rsl; lhi = lhi*sfh + rsh;
        mlo = mnl; mhi = mnh;
        #pragma unroll
        for (int nt = 0; nt < 8; nt++) {
            acc[nt][0] *= sfl; acc[nt][1] *= sfl;
            acc[nt][2] *= sfh; acc[nt][3] *= sfh;
        }

        __syncthreads();        // all warps done reading Ks -> overwrite with P
        #pragma unroll
        for (int nt = 0; nt < 8; nt++) {
            Ks[wm+g  ][nt*4 + tig] = h2(s[nt][0], s[nt][1]);
            Ks[wm+g+8][nt*4 + tig] = h2(s[nt][2], s[nt][3]);
        }
        __syncwarp();           // P rows are warp-local

        // acc(16x64) += P(16x64) . V(64x64)
        #pragma unroll
        for (int ks = 0; ks < 4; ks++) {
            int kp = ks*8 + tig;
            unsigned a[4] = { Ks[wm+g][kp], Ks[wm+g+8][kp],
                              Ks[wm+g][kp+4], Ks[wm+g+8][kp+4] };
            #pragma unroll
            for (int nt = 0; nt < 8; nt++) {
                unsigned bf[2] = { Vt[nt*8+g][kp], Vt[nt*8+g][kp+4] };
                mma_f16(acc[nt], a, bf);
            }
        }
    }

    float il = 1.0f / llo, ih = 1.0f / lhi;
    float* clo = &g_ctx[((size_t)(b*S_ + r_lo))*E_ + h*D_];
    float* chi = &g_ctx[((size_t)(b*S_ + r_hi))*E_ + h*D_];
    #pragma unroll
    for (int nt = 0; nt < 8; nt++) {
        int d = nt*8 + tig*2;
        *(float2*)&clo[d] = make_float2(acc[nt][0]*il, acc[nt][1]*il);
        *(float2*)&chi[d] = make_float2(acc[nt][2]*ih, acc[nt][3]*ih);
    }
    if (tig == 0) {
        g_m[(size_t)bh*S_ + r_lo] = mlo; g_l[(size_t)bh*S_ + r_lo] = llo;
        g_m[(size_t)bh*S_ + r_hi] = mhi; g_l[(size_t)bh*S_ + r_hi] = lhi;
    }
}

// ---------------- K3: attn mean over heads (fp16 mma recompute), 8 warps ----
// 64x64 tile; warp w covers q-rows (w&3)*16 x k-cols (w>>2)*32.
__global__ __launch_bounds__(256) void attnmean_kernel(float* __restrict__ out_attn) {
    int kt = blockIdx.x, m0 = blockIdx.y * 64, b = blockIdx.z;
    __shared__ unsigned Qs[64][36];
    __shared__ unsigned Ks[64][36];
    int t = threadIdx.x, w = t >> 5, lane = t & 31, g = lane >> 2, tig = lane & 3;
    int qm = (w & 3) * 16, kn = (w >> 2) * 32;
    int r_lo = m0 + qm + g, r_hi = r_lo + 8;
    const float* mb = g_maskbias + b * S_;

    float acc[4][4] = {};
    for (int h = 0; h < H_; h++) {
        int bh = b*H_ + h;
        const float* Q  = g_q + (size_t)bh * S_ * D_;
        const float* Kp = g_k + (size_t)bh * S_ * D_ + (size_t)kt * 64 * D_;
        __syncthreads();
        {
            int r = t >> 2, c0 = (t & 3) * 16;
            #pragma unroll
            for (int j = 0; j < 4; j++) {
                float4 qv = *(const float4*)(Q + (size_t)(m0 + r) * D_ + c0 + j*4);
                Qs[r][(c0 + j*4)/2]     = h2(qv.x, qv.y);
                Qs[r][(c0 + j*4)/2 + 1] = h2(qv.z, qv.w);
                float4 kv = *(const float4*)(Kp + (size_t)r * D_ + c0 + j*4);
                Ks[r][(c0 + j*4)/2]     = h2(kv.x, kv.y);
                Ks[r][(c0 + j*4)/2 + 1] = h2(kv.z, kv.w);
            }
        }
        __syncthreads();

        float s[4][4] = {};
        #pragma unroll
        for (int ks = 0; ks < 4; ks++) {
            int kp = ks*8 + tig;
            unsigned a[4] = { Qs[qm+g][kp], Qs[qm+g+8][kp],
                              Qs[qm+g][kp+4], Qs[qm+g+8][kp+4] };
            #pragma unroll
            for (int nt = 0; nt < 4; nt++) {
                unsigned bf[2] = { Ks[kn+nt*8+g][kp], Ks[kn+nt*8+g][kp+4] };
                mma_f16(s[nt], a, bf);
            }
        }

        float ml = g_m[(size_t)bh*S_ + r_lo], il = 1.0f / g_l[(size_t)bh*S_ + r_lo];
        float mh = g_m[(size_t)bh*S_ + r_hi], ih = 1.0f / g_l[(size_t)bh*S_ + r_hi];
        #pragma unroll
        for (int nt = 0; nt < 4; nt++) {
            int c = kt*64 + kn + nt*8 + tig*2;
            float mb0 = mb[c], mb1 = mb[c+1];
            acc[nt][0] += __expf(s[nt][0]*0.125f + (float)(r_lo - c    ) + mb0 - ml) * il;
            acc[nt][1] += __expf(s[nt][1]*0.125f + (float)(r_lo - c - 1) + mb1 - ml) * il;
            acc[nt][2] += __expf(s[nt][2]*0.125f + (float)(r_hi - c    ) + mb0 - mh) * ih;
            acc[nt][3] += __expf(s[nt][3]*0.125f + (float)(r_hi - c - 1) + mb1 - mh) * ih;
        }
    }
    float* olo = &out_attn[((size_t)(b*S_ + r_lo))*S_ + kt*64 + kn];
    float* ohi = &out_attn[((size_t)(b*S_ + r_hi))*S_ + kt*64 + kn];
    #pragma unroll
    for (int nt = 0; nt < 4; nt++) {
        int c = nt*8 + tig*2;
        *(float2*)&olo[c] = make_float2(acc[nt][0]*0.0625f, acc[nt][1]*0.0625f);
        *(float2*)&ohi[c] = make_float2(acc[nt][2]*0.0625f, acc[nt][3]*0.0625f);
    }
}

// ---------------- K4: out = ctx @ Wo^T + bo (fp16 mma) ----------------------
__global__ __launch_bounds__(256) void out_gemm(
    const float* __restrict__ W, const float* __restrict__ bias,
    float* __restrict__ out)
{
    __shared__ unsigned As[128][20];
    __shared__ unsigned Ws[64][20];
    int t = threadIdx.x, w = t >> 5, lane = t & 31, g = lane >> 2, tig = lane & 3;
    int wm = (w & 3) * 32, wn = (w >> 2) * 32;
    int m0 = blockIdx.y * 128, n0 = blockIdx.x * 64;

    float acc[2][4][4] = {};
    int ar = t >> 3, ac2 = (t & 7) * 2;
    int wr = t >> 2, wc2 = (t & 3) * 4;

    for (int k0 = 0; k0 < E_; k0 += 32) {
        #pragma unroll
        for (int p = 0; p < 4; p++) {
            float4 v = *(const float4*)(g_ctx + (size_t)(m0 + ar + p*32) * E_ + k0 + ac2*2);
            As[ar + p*32][ac2]   = h2(v.x, v.y);
            As[ar + p*32][ac2+1] = h2(v.z, v.w);
        }
        {
            float4 v0 = *(const float4*)(W + (size_t)(n0 + wr) * E_ + k0 + wc2*2);
            float4 v1 = *(const float4*)(W + (size_t)(n0 + wr) * E_ + k0 + wc2*2 + 4);
            Ws[wr][wc2]   = h2(v0.x, v0.y); Ws[wr][wc2+1] = h2(v0.z, v0.w);
            Ws[wr][wc2+2] = h2(v1.x, v1.y); Ws[wr][wc2+3] = h2(v1.z, v1.w);
        }
        __syncthreads();
        #pragma unroll
        for (int ks = 0; ks < 2; ks++) {
            int kp = ks*8 + tig;
            unsigned a[2][4], bf[4][2];
            #pragma unroll
            for (int mt = 0; mt < 2; mt++) {
                int r = wm + mt*16 + g;
                a[mt][0] = As[r  ][kp];   a[mt][1] = As[r+8][kp];
                a[mt][2] = As[r  ][kp+4]; a[mt][3] = As[r+8][kp+4];
            }
            #pragma unroll
            for (int nt = 0; nt < 4; nt++) {
                int n = wn + nt*8 + g;
                bf[nt][0] = Ws[n][kp]; bf[nt][1] = Ws[n][kp+4];
            }
            #pragma unroll
            for (int mt = 0; mt < 2; mt++)
                #pragma unroll
                for (int nt = 0; nt < 4; nt++)
                    mma_f16(acc[mt][nt], a[mt], bf[nt]);
        }
        __syncthreads();
    }
    #pragma unroll
    for (int mt = 0; mt < 2; mt++) {
        int m_ = m0 + wm + mt*16 + g;
        #pragma unroll
        for (int nt = 0; nt < 4; nt++) {
            int n_ = n0 + wn + nt*8 + tig*2;
            float bx = bias[n_], by = bias[n_+1];
            *(float2*)&out[(size_t)m_ * E_ + n_] =
                make_float2(acc[mt][nt][0] + bx, acc[mt][nt][1] + by);
            *(float2*)&out[(size_t)(m_+8) * E_ + n_] =
                make_float2(acc[mt][nt][2] + bx, acc[mt][nt][3] + by);
        }
    }
}

// ---------------- launch ----------------------------------------------------
extern "C" void kernel_launch(void* const* d_in, const int* in_sizes, int n_in,
                              void* d_out, int out_size)
{
    const float* query = (const float*)d_in[0];
    const float* key   = (const float*)d_in[1];
    const float* value = (const float*)d_in[2];
    const void*  mask  = d_in[3];
    const float* win   = (const float*)d_in[4];
    const float* bin   = (const float*)d_in[5];
    const float* wout  = (const float*)d_in[6];
    const float* bout  = (const float*)d_in[7];

    float* out      = (float*)d_out;                      // [4,1024,1024] output
    float* out_attn = out + (size_t)B_ * S_ * E_;         // [4,1024,1024] attn mean

    mask_kernel<<<1, 1024>>>(mask);
    qkv_gemm<<<dim3(16, 32, 3), 256>>>(query, key, value, win, bin);
    flash_kernel<<<dim3(16, 64), 128>>>();
    attnmean_kernel<<<dim3(16, 16, 4), 256>>>(out_attn);
    out_gemm<<<dim3(16, 32), 256>>>(wout, bout, out);
}

// round 8
// speedup vs baseline: 1.8088x; 1.3176x over previous
#include <cuda_runtime.h>
#include <cuda_fp16.h>
#include <math.h>

#define B_ 4
#define S_ 1024
#define E_ 1024
#define H_ 16
#define D_ 64

// ---------------- scratch (alloc-free: __device__ globals, ~64.5 MB) -------
__device__ __align__(16) __half g_inh[3*B_*S_*E_];   // 24 MB pre-converted q/k/v inputs
__device__ __align__(16) __half g_wh[3*E_*E_];       // 6 MB  in_proj weights (half)
__device__ __align__(16) __half g_woh[E_*E_];        // 2 MB  out_proj weights (half)
__device__ __align__(16) __half g_qh[B_*H_*S_*D_];   // 8 MB  [b,h,s,d]
__device__ __align__(16) __half g_kh[B_*H_*S_*D_];   // 8 MB  [b,h,s,d]
__device__ __align__(16) __half g_vh[B_*H_*S_*D_];   // 8 MB  [b,h,d,s]  (transposed!)
__device__ __align__(16) __half g_ctxh[B_*S_*E_];    // 8 MB  [b,s,h*D+d]
__device__ float g_m[B_*H_*S_];
__device__ float g_l[B_*H_*S_];
__device__ float g_maskbias[B_*S_];

// ---------------- fp16 helpers ----------------
__device__ __forceinline__ unsigned h2(float a, float b) {
    __half2 h = __floats2half2_rn(a, b);
    return *reinterpret_cast<unsigned*>(&h);
}

// D += A(16x16, row) * B(16x8, col); c[4] fp32, a[4]/b[2] = half2 regs
__device__ __forceinline__ void mma_f16(float* c, const unsigned* a, const unsigned* b) {
    asm volatile(
        "mma.sync.aligned.m16n8k16.row.col.f32.f16.f16.f32 "
        "{%0,%1,%2,%3}, {%4,%5,%6,%7}, {%8,%9}, {%0,%1,%2,%3};"
        : "+f"(c[0]), "+f"(c[1]), "+f"(c[2]), "+f"(c[3])
        : "r"(a[0]), "r"(a[1]), "r"(a[2]), "r"(a[3]), "r"(b[0]), "r"(b[1]));
}

// ---------------- K0a: fp32 -> fp16 bulk convert ----------------------------
__global__ void f2h_kernel(const float* __restrict__ in, __half* __restrict__ out, int n4) {
    int i = blockIdx.x * blockDim.x + threadIdx.x;
    if (i < n4) {
        float4 v = ((const float4*)in)[i];
        *(__half2*)(out + (size_t)i*4)     = __floats2half2_rn(v.x, v.y);
        *(__half2*)(out + (size_t)i*4 + 2) = __floats2half2_rn(v.z, v.w);
    }
}

// ---------------- K0b: mask dtype detection + expansion ----------------------
__global__ void mask_kernel(const void* __restrict__ mask_raw) {
    __shared__ int s_int, s_flt;
    int t = threadIdx.x;
    if (t == 0) { s_int = 1; s_flt = 1; }
    __syncthreads();
    const unsigned int* w = (const unsigned int*)mask_raw;
    unsigned int v = w[t];
    if (!(v == 0u || v == 1u))           atomicAnd(&s_int, 0);
    if (!(v == 0u || v == 0x3f800000u))  atomicAnd(&s_flt, 0);
    __syncthreads();
    int mode = s_int ? 0 : (s_flt ? 1 : 2);
    for (int i = t; i < B_*S_; i += 1024) {
        bool keep;
        if (mode == 0)      keep = ((const int*)mask_raw)[i] != 0;
        else if (mode == 1) keep = ((const float*)mask_raw)[i] != 0.0f;
        else                keep = ((const unsigned char*)mask_raw)[i] != 0;
        g_maskbias[i] = keep ? 0.0f : -INFINITY;
    }
}

// ---------------- K1: QKV projection (fp16 mma, half in/out) ----------------
// BM=128 BN=64 BK=32; 8 warps (4m x 2n). z=2 (V) written transposed [bh,d,s].
__global__ __launch_bounds__(256) void qkv_gemm(const float* __restrict__ bias) {
    int z = blockIdx.z;
    const __half* A  = g_inh + (size_t)z * B_ * S_ * E_;
    const __half* Wz = g_wh + (size_t)z * E_ * E_;
    const float*  bz = bias + z * E_;

    __shared__ unsigned As[128][20];   // 128 rows x 16 half2 (+4 pad)
    __shared__ unsigned Ws[64][20];
    int t = threadIdx.x, w = t >> 5, lane = t & 31, g = lane >> 2, tig = lane & 3;
    int wm = (w & 3) * 32, wn = (w >> 2) * 32;
    int m0 = blockIdx.y * 128, n0 = blockIdx.x * 64;

    float acc[2][4][4] = {};
    int ar = t >> 3, ac2 = (t & 7) * 2;     // A: 8 threads/row, uint2 (4 halves)
    int wr = t >> 2, wc2 = (t & 3) * 4;     // W: 4 threads/row, uint4 (8 halves)

    for (int k0 = 0; k0 < E_; k0 += 32) {
        #pragma unroll
        for (int p = 0; p < 4; p++) {
            uint2 v = *(const uint2*)(A + (size_t)(m0 + ar + p*32) * E_ + k0 + ac2*2);
            As[ar + p*32][ac2] = v.x; As[ar + p*32][ac2+1] = v.y;
        }
        {
            uint4 v = *(const uint4*)(Wz + (size_t)(n0 + wr) * E_ + k0 + wc2*2);
            Ws[wr][wc2] = v.x; Ws[wr][wc2+1] = v.y; Ws[wr][wc2+2] = v.z; Ws[wr][wc2+3] = v.w;
        }
        __syncthreads();
        #pragma unroll
        for (int ks = 0; ks < 2; ks++) {
            int kp = ks*8 + tig;
            unsigned a[2][4], bf[4][2];
            #pragma unroll
            for (int mt = 0; mt < 2; mt++) {
                int r = wm + mt*16 + g;
                a[mt][0] = As[r  ][kp];   a[mt][1] = As[r+8][kp];
                a[mt][2] = As[r  ][kp+4]; a[mt][3] = As[r+8][kp+4];
            }
            #pragma unroll
            for (int nt = 0; nt < 4; nt++) {
                int n = wn + nt*8 + g;
                bf[nt][0] = Ws[n][kp]; bf[nt][1] = Ws[n][kp+4];
            }
            #pragma unroll
            for (int mt = 0; mt < 2; mt++)
                #pragma unroll
                for (int nt = 0; nt < 4; nt++)
                    mma_f16(acc[mt][nt], a[mt], bf[nt]);
        }
        __syncthreads();
    }
    #pragma unroll
    for (int mt = 0; mt < 2; mt++) {
        int m_ = m0 + wm + mt*16 + g;
        int bb = m_ >> 10, s0 = m_ & 1023;
        #pragma unroll
        for (int nt = 0; nt < 4; nt++) {
            int n_ = n0 + wn + nt*8 + tig*2;
            int h = n_ >> 6, d = n_ & 63;
            float bx = bz[n_], by = bz[n_+1];
            if (z == 2) {       // V transposed: [bh, d, s]
                size_t base = ((size_t)(bb*H_ + h)*D_);
                g_vh[(base + d  )*S_ + s0    ] = __float2half_rn(acc[mt][nt][0] + bx);
                g_vh[(base + d+1)*S_ + s0    ] = __float2half_rn(acc[mt][nt][1] + by);
                g_vh[(base + d  )*S_ + s0 + 8] = __float2half_rn(acc[mt][nt][2] + bx);
                g_vh[(base + d+1)*S_ + s0 + 8] = __float2half_rn(acc[mt][nt][3] + by);
            } else {
                __half* outp = (z == 0) ? g_qh : g_kh;
                size_t base = ((size_t)(bb*H_ + h)*S_);
                *(__half2*)&outp[(base + s0    )*D_ + d] =
                    __floats2half2_rn(acc[mt][nt][0] + bx, acc[mt][nt][1] + by);
                *(__half2*)&outp[(base + s0 + 8)*D_ + d] =
                    __floats2half2_rn(acc[mt][nt][2] + bx, acc[mt][nt][3] + by);
            }
        }
    }
}

// ---------------- K2: fused flash attention (fp16 mma), 4 warps -------------
__global__ __launch_bounds__(128) void flash_kernel() {
    int bh = blockIdx.y; int b = bh >> 4, h = bh & 15;
    int m0 = blockIdx.x * 64;
    const __half* Q  = g_qh + (size_t)bh * S_ * D_;
    const __half* Kp = g_kh + (size_t)bh * S_ * D_;
    const __half* Vp = g_vh + (size_t)bh * D_ * S_;   // [d][s]
    const float* mb = g_maskbias + b * S_;

    __shared__ unsigned Ks[64][36];   // K tile [key][k-pair]; reused as P tile
    __shared__ unsigned Vt[64][36];   // V [d][s-pair]

    int t = threadIdx.x, w = t >> 5, lane = t & 31, g = lane >> 2, tig = lane & 3;
    int wm = w * 16;
    int r_lo = m0 + wm + g, r_hi = r_lo + 8;

    // stage Q through Ks, hoist A-fragments to registers
    {
        int r = t >> 1, c0 = (t & 1) * 32;
        #pragma unroll
        for (int j = 0; j < 4; j++) {
            uint4 v = *(const uint4*)(Q + (size_t)(m0 + r) * D_ + c0 + j*8);
            int cc = c0/2 + j*4;
            Ks[r][cc] = v.x; Ks[r][cc+1] = v.y; Ks[r][cc+2] = v.z; Ks[r][cc+3] = v.w;
        }
    }
    __syncthreads();
    unsigned aq[4][4];
    #pragma unroll
    for (int ks = 0; ks < 4; ks++) {
        int kp = ks*8 + tig;
        aq[ks][0] = Ks[wm+g  ][kp];   aq[ks][1] = Ks[wm+g+8][kp];
        aq[ks][2] = Ks[wm+g  ][kp+4]; aq[ks][3] = Ks[wm+g+8][kp+4];
    }

    float acc[8][4] = {};
    float mlo = -1e30f, mhi = -1e30f, llo = 0.0f, lhi = 0.0f;

    for (int kt = 0; kt < 16; kt++) {
        __syncthreads();        // prior readers of Ks/Vt done (incl. aq, iter 0)
        {   // K tile rows = keys; V tile rows = d, cols = keys (both contiguous)
            int r = t >> 1, c0 = (t & 1) * 32;
            #pragma unroll
            for (int j = 0; j < 4; j++) {
                int cc = c0/2 + j*4;
                uint4 kv = *(const uint4*)(Kp + (size_t)(kt*64 + r) * D_ + c0 + j*8);
                Ks[r][cc] = kv.x; Ks[r][cc+1] = kv.y; Ks[r][cc+2] = kv.z; Ks[r][cc+3] = kv.w;
                uint4 vv = *(const uint4*)(Vp + (size_t)r * S_ + kt*64 + c0 + j*8);
                Vt[r][cc] = vv.x; Vt[r][cc+1] = vv.y; Vt[r][cc+2] = vv.z; Vt[r][cc+3] = vv.w;
            }
        }
        __syncthreads();

        // S(16x64 per warp) = Q . K^T
        float s[8][4] = {};
        #pragma unroll
        for (int ks = 0; ks < 4; ks++) {
            int kp = ks*8 + tig;
            #pragma unroll
            for (int nt = 0; nt < 8; nt++) {
                unsigned bf[2] = { Ks[nt*8+g][kp], Ks[nt*8+g][kp+4] };
                mma_f16(s[nt], aq[ks], bf);
            }
        }

        // scale + rel bias + mask, online softmax over 64 cols
        float rml = -1e30f, rmh = -1e30f;
        #pragma unroll
        for (int nt = 0; nt < 8; nt++) {
            int c = kt*64 + nt*8 + tig*2;
            float mb0 = mb[c], mb1 = mb[c+1];
            s[nt][0] = s[nt][0]*0.125f + (float)(r_lo - c    ) + mb0;
            s[nt][1] = s[nt][1]*0.125f + (float)(r_lo - c - 1) + mb1;
            s[nt][2] = s[nt][2]*0.125f + (float)(r_hi - c    ) + mb0;
            s[nt][3] = s[nt][3]*0.125f + (float)(r_hi - c - 1) + mb1;
            rml = fmaxf(rml, fmaxf(s[nt][0], s[nt][1]));
            rmh = fmaxf(rmh, fmaxf(s[nt][2], s[nt][3]));
        }
        rml = fmaxf(rml, __shfl_xor_sync(0xffffffffu, rml, 1));
        rml = fmaxf(rml, __shfl_xor_sync(0xffffffffu, rml, 2));
        rmh = fmaxf(rmh, __shfl_xor_sync(0xffffffffu, rmh, 1));
        rmh = fmaxf(rmh, __shfl_xor_sync(0xffffffffu, rmh, 2));

        float mnl = fmaxf(mlo, rml), mnh = fmaxf(mhi, rmh);
        float sfl = __expf(mlo - mnl), sfh = __expf(mhi - mnh);
        float rsl = 0.0f, rsh = 0.0f;
        #pragma unroll
        for (int nt = 0; nt < 8; nt++) {
            s[nt][0] = __expf(s[nt][0] - mnl); s[nt][1] = __expf(s[nt][1] - mnl);
            s[nt][2] = __expf(s[nt][2] - mnh); s[nt][3] = __expf(s[nt][3] - mnh);
            rsl += s[nt][0] + s[nt][1]; rsh += s[nt][2] + s[nt][3];
        }
        rsl += __shfl_xor_sync(0xffffffffu, rsl, 1);
        rsl += __shfl_xor_sync(0xffffffffu, rsl, 2);
        rsh += __shfl_xor_sync(0xffffffffu, rsh, 1);
        rsh += __shfl_xor_sync(0xffffffffu, rsh, 2);
        llo = llo*sfl + rsl; lhi = lhi*sfh + rsh;
        mlo = mnl; mhi = mnh;
        #pragma unroll
        for (int nt = 0; nt < 8; nt++) {
            acc[nt][0] *= sfl; acc[nt][1] *= sfl;
            acc[nt][2] *= sfh; acc[nt][3] *= sfh;
        }

        __syncthreads();        // all warps done reading Ks -> overwrite with P
        #pragma unroll
        for (int nt = 0; nt < 8; nt++) {
            Ks[wm+g  ][nt*4 + tig] = h2(s[nt][0], s[nt][1]);
            Ks[wm+g+8][nt*4 + tig] = h2(s[nt][2], s[nt][3]);
        }
        __syncwarp();           // P rows are warp-local

        // acc(16x64) += P(16x64) . V(64x64)
        #pragma unroll
        for (int ks = 0; ks < 4; ks++) {
            int kp = ks*8 + tig;
            unsigned a[4] = { Ks[wm+g][kp], Ks[wm+g+8][kp],
                              Ks[wm+g][kp+4], Ks[wm+g+8][kp+4] };
            #pragma unroll
            for (int nt = 0; nt < 8; nt++) {
                unsigned bf[2] = { Vt[nt*8+g][kp], Vt[nt*8+g][kp+4] };
                mma_f16(acc[nt], a, bf);
            }
        }
    }

    float il = 1.0f / llo, ih = 1.0f / lhi;
    __half* clo = &g_ctxh[((size_t)(b*S_ + r_lo))*E_ + h*D_];
    __half* chi = &g_ctxh[((size_t)(b*S_ + r_hi))*E_ + h*D_];
    #pragma unroll
    for (int nt = 0; nt < 8; nt++) {
        int d = nt*8 + tig*2;
        *(__half2*)&clo[d] = __floats2half2_rn(acc[nt][0]*il, acc[nt][1]*il);
        *(__half2*)&chi[d] = __floats2half2_rn(acc[nt][2]*ih, acc[nt][3]*ih);
    }
    if (tig == 0) {
        g_m[(size_t)bh*S_ + r_lo] = mlo; g_l[(size_t)bh*S_ + r_lo] = llo;
        g_m[(size_t)bh*S_ + r_hi] = mhi; g_l[(size_t)bh*S_ + r_hi] = lhi;
    }
}

// ---------------- K3: attn mean over heads (fp16 mma recompute), 8 warps ----
__global__ __launch_bounds__(256) void attnmean_kernel(float* __restrict__ out_attn) {
    int kt = blockIdx.x, m0 = blockIdx.y * 64, b = blockIdx.z;
    __shared__ unsigned Qs[64][36];
    __shared__ unsigned Ks[64][36];
    int t = threadIdx.x, w = t >> 5, lane = t & 31, g = lane >> 2, tig = lane & 3;
    int qm = (w & 3) * 16, kn = (w >> 2) * 32;
    int r_lo = m0 + qm + g, r_hi = r_lo + 8;
    const float* mb = g_maskbias + b * S_;

    float acc[4][4] = {};
    for (int h = 0; h < H_; h++) {
        int bh = b*H_ + h;
        const __half* Q  = g_qh + (size_t)bh * S_ * D_;
        const __half* Kp = g_kh + (size_t)bh * S_ * D_ + (size_t)kt * 64 * D_;
        __syncthreads();
        {
            int r = t >> 2, c0 = (t & 3) * 16;
            #pragma unroll
            for (int j = 0; j < 2; j++) {
                int cc = c0/2 + j*4;
                uint4 qv = *(const uint4*)(Q + (size_t)(m0 + r) * D_ + c0 + j*8);
                Qs[r][cc] = qv.x; Qs[r][cc+1] = qv.y; Qs[r][cc+2] = qv.z; Qs[r][cc+3] = qv.w;
                uint4 kv = *(const uint4*)(Kp + (size_t)r * D_ + c0 + j*8);
                Ks[r][cc] = kv.x; Ks[r][cc+1] = kv.y; Ks[r][cc+2] = kv.z; Ks[r][cc+3] = kv.w;
            }
        }
        __syncthreads();

        float s[4][4] = {};
        #pragma unroll
        for (int ks = 0; ks < 4; ks++) {
            int kp = ks*8 + tig;
            unsigned a[4] = { Qs[qm+g][kp], Qs[qm+g+8][kp],
                              Qs[qm+g][kp+4], Qs[qm+g+8][kp+4] };
            #pragma unroll
            for (int nt = 0; nt < 4; nt++) {
                unsigned bf[2] = { Ks[kn+nt*8+g][kp], Ks[kn+nt*8+g][kp+4] };
                mma_f16(s[nt], a, bf);
            }
        }

        float ml = g_m[(size_t)bh*S_ + r_lo], il = 1.0f / g_l[(size_t)bh*S_ + r_lo];
        float mh = g_m[(size_t)bh*S_ + r_hi], ih = 1.0f / g_l[(size_t)bh*S_ + r_hi];
        #pragma unroll
        for (int nt = 0; nt < 4; nt++) {
            int c = kt*64 + kn + nt*8 + tig*2;
            float mb0 = mb[c], mb1 = mb[c+1];
            acc[nt][0] += __expf(s[nt][0]*0.125f + (float)(r_lo - c    ) + mb0 - ml) * il;
            acc[nt][1] += __expf(s[nt][1]*0.125f + (float)(r_lo - c - 1) + mb1 - ml) * il;
            acc[nt][2] += __expf(s[nt][2]*0.125f + (float)(r_hi - c    ) + mb0 - mh) * ih;
            acc[nt][3] += __expf(s[nt][3]*0.125f + (float)(r_hi - c - 1) + mb1 - mh) * ih;
        }
    }
    float* olo = &out_attn[((size_t)(b*S_ + r_lo))*S_ + kt*64 + kn];
    float* ohi = &out_attn[((size_t)(b*S_ + r_hi))*S_ + kt*64 + kn];
    #pragma unroll
    for (int nt = 0; nt < 4; nt++) {
        int c = nt*8 + tig*2;
        *(float2*)&olo[c] = make_float2(acc[nt][0]*0.0625f, acc[nt][1]*0.0625f);
        *(float2*)&ohi[c] = make_float2(acc[nt][2]*0.0625f, acc[nt][3]*0.0625f);
    }
}

// ---------------- K4: out = ctx @ Wo^T + bo (fp16 mma, half in) -------------
__global__ __launch_bounds__(256) void out_gemm(
    const float* __restrict__ bias, float* __restrict__ out)
{
    __shared__ unsigned As[128][20];
    __shared__ unsigned Ws[64][20];
    int t = threadIdx.x, w = t >> 5, lane = t & 31, g = lane >> 2, tig = lane & 3;
    int wm = (w & 3) * 32, wn = (w >> 2) * 32;
    int m0 = blockIdx.y * 128, n0 = blockIdx.x * 64;

    float acc[2][4][4] = {};
    int ar = t >> 3, ac2 = (t & 7) * 2;
    int wr = t >> 2, wc2 = (t & 3) * 4;

    for (int k0 = 0; k0 < E_; k0 += 32) {
        #pragma unroll
        for (int p = 0; p < 4; p++) {
            uint2 v = *(const uint2*)(g_ctxh + (size_t)(m0 + ar + p*32) * E_ + k0 + ac2*2);
            As[ar + p*32][ac2] = v.x; As[ar + p*32][ac2+1] = v.y;
        }
        {
            uint4 v = *(const uint4*)(g_woh + (size_t)(n0 + wr) * E_ + k0 + wc2*2);
            Ws[wr][wc2] = v.x; Ws[wr][wc2+1] = v.y; Ws[wr][wc2+2] = v.z; Ws[wr][wc2+3] = v.w;
        }
        __syncthreads();
        #pragma unroll
        for (int ks = 0; ks < 2; ks++) {
            int kp = ks*8 + tig;
            unsigned a[2][4], bf[4][2];
            #pragma unroll
            for (int mt = 0; mt < 2; mt++) {
                int r = wm + mt*16 + g;
                a[mt][0] = As[r  ][kp];   a[mt][1] = As[r+8][kp];
                a[mt][2] = As[r  ][kp+4]; a[mt][3] = As[r+8][kp+4];
            }
            #pragma unroll
            for (int nt = 0; nt < 4; nt++) {
                int n = wn + nt*8 + g;
                bf[nt][0] = Ws[n][kp]; bf[nt][1] = Ws[n][kp+4];
            }
            #pragma unroll
            for (int mt = 0; mt < 2; mt++)
                #pragma unroll
                for (int nt = 0; nt < 4; nt++)
                    mma_f16(acc[mt][nt], a[mt], bf[nt]);
        }
        __syncthreads();
    }
    #pragma unroll
    for (int mt = 0; mt < 2; mt++) {
        int m_ = m0 + wm + mt*16 + g;
        #pragma unroll
        for (int nt = 0; nt < 4; nt++) {
            int n_ = n0 + wn + nt*8 + tig*2;
            float bx = bias[n_], by = bias[n_+1];
            *(float2*)&out[(size_t)m_ * E_ + n_] =
                make_float2(acc[mt][nt][0] + bx, acc[mt][nt][1] + by);
            *(float2*)&out[(size_t)(m_+8) * E_ + n_] =
                make_float2(acc[mt][nt][2] + bx, acc[mt][nt][3] + by);
        }
    }
}

// ---------------- launch ----------------------------------------------------
extern "C" void kernel_launch(void* const* d_in, const int* in_sizes, int n_in,
                              void* d_out, int out_size)
{
    const float* query = (const float*)d_in[0];
    const float* key   = (const float*)d_in[1];
    const float* value = (const float*)d_in[2];
    const void*  mask  = d_in[3];
    const float* win   = (const float*)d_in[4];
    const float* bin   = (const float*)d_in[5];
    const float* wout  = (const float*)d_in[6];
    const float* bout  = (const float*)d_in[7];

    float* out      = (float*)d_out;                      // [4,1024,1024] output
    float* out_attn = out + (size_t)B_ * S_ * E_;         // [4,1024,1024] attn mean

    const int NIN = B_*S_*E_/4;      // 1M float4 per input
    __half* inh = nullptr; __half* wh = nullptr; __half* woh = nullptr;
    cudaGetSymbolAddress((void**)&inh, g_inh);
    cudaGetSymbolAddress((void**)&wh,  g_wh);
    cudaGetSymbolAddress((void**)&woh, g_woh);

    mask_kernel<<<1, 1024>>>(mask);
    f2h_kernel<<<(NIN+255)/256, 256>>>(query, inh, NIN);
    f2h_kernel<<<(NIN+255)/256, 256>>>(key,   inh + (size_t)B_*S_*E_, NIN);
    f2h_kernel<<<(NIN+255)/256, 256>>>(value, inh + (size_t)2*B_*S_*E_, NIN);
    f2h_kernel<<<(3*E_*E_/4+255)/256, 256>>>(win,  wh,  3*E_*E_/4);
    f2h_kernel<<<(E_*E_/4+255)/256, 256>>>(wout, woh, E_*E_/4);
    qkv_gemm<<<dim3(16, 32, 3), 256>>>(bin);
    flash_kernel<<<dim3(16, 64), 128>>>();
    attnmean_kernel<<<dim3(16, 16, 4), 256>>>(out_attn);
    out_gemm<<<dim3(16, 32), 256>>>(bout, out);
}

// round 10
// speedup vs baseline: 2.0071x; 1.1096x over previous
#include <cuda_runtime.h>
#include <cuda_fp16.h>
#include <math.h>

#define B_ 4
#define S_ 1024
#define E_ 1024
#define H_ 16
#define D_ 64

// ---------------- scratch (alloc-free: __device__ globals, ~196 MB) --------
__device__ __align__(16) __half g_inh[3*B_*S_*E_];   // 24 MB pre-converted q/k/v inputs
__device__ __align__(16) __half g_wh[3*E_*E_];       // 6 MB  in_proj weights (half)
__device__ __align__(16) __half g_woh[E_*E_];        // 2 MB  out_proj weights (half)
__device__ __align__(16) __half g_qh[B_*H_*S_*D_];   // 8 MB  [b,h,s,d]
__device__ __align__(16) __half g_kh[B_*H_*S_*D_];   // 8 MB  [b,h,s,d]
__device__ __align__(16) __half g_vh[B_*H_*S_*D_];   // 8 MB  [b,h,d,s]  (transposed!)
__device__ __align__(16) __half g_ctxh[B_*S_*E_];    // 8 MB  [b,s,h*D+d]
__device__ __align__(16) __half g_ph[(size_t)B_*H_*S_*S_];  // 128 MB unnormalized P tiles
__device__ float g_mt[B_*H_*16*S_];                  // 4 MB  per-tile row max [bh,kt,q]
__device__ float g_m[B_*H_*S_];
__device__ float g_l[B_*H_*S_];
__device__ float g_maskbias[B_*S_];

// ---------------- fp16 helpers ----------------
__device__ __forceinline__ unsigned h2(float a, float b) {
    __half2 h = __floats2half2_rn(a, b);
    return *reinterpret_cast<unsigned*>(&h);
}

// D += A(16x16, row) * B(16x8, col); c[4] fp32, a[4]/b[2] = half2 regs
__device__ __forceinline__ void mma_f16(float* c, const unsigned* a, const unsigned* b) {
    asm volatile(
        "mma.sync.aligned.m16n8k16.row.col.f32.f16.f16.f32 "
        "{%0,%1,%2,%3}, {%4,%5,%6,%7}, {%8,%9}, {%0,%1,%2,%3};"
        : "+f"(c[0]), "+f"(c[1]), "+f"(c[2]), "+f"(c[3])
        : "r"(a[0]), "r"(a[1]), "r"(a[2]), "r"(a[3]), "r"(b[0]), "r"(b[1]));
}

// ---------------- K0a: fp32 -> fp16 bulk convert ----------------------------
__global__ void f2h_kernel(const float* __restrict__ in, __half* __restrict__ out, int n4) {
    int i = blockIdx.x * blockDim.x + threadIdx.x;
    if (i < n4) {
        float4 v = ((const float4*)in)[i];
        *(__half2*)(out + (size_t)i*4)     = __floats2half2_rn(v.x, v.y);
        *(__half2*)(out + (size_t)i*4 + 2) = __floats2half2_rn(v.z, v.w);
    }
}

// ---------------- K0b: mask dtype detection + expansion ----------------------
__global__ void mask_kernel(const void* __restrict__ mask_raw) {
    __shared__ int s_int, s_flt;
    int t = threadIdx.x;
    if (t == 0) { s_int = 1; s_flt = 1; }
    __syncthreads();
    const unsigned int* w = (const unsigned int*)mask_raw;
    unsigned int v = w[t];
    if (!(v == 0u || v == 1u))           atomicAnd(&s_int, 0);
    if (!(v == 0u || v == 0x3f800000u))  atomicAnd(&s_flt, 0);
    __syncthreads();
    int mode = s_int ? 0 : (s_flt ? 1 : 2);
    for (int i = t; i < B_*S_; i += 1024) {
        bool keep;
        if (mode == 0)      keep = ((const int*)mask_raw)[i] != 0;
        else if (mode == 1) keep = ((const float*)mask_raw)[i] != 0.0f;
        else                keep = ((const unsigned char*)mask_raw)[i] != 0;
        g_maskbias[i] = keep ? 0.0f : -INFINITY;
    }
}

// ---------------- K1: QKV projection (fp16 mma, half in/out) ----------------
__global__ __launch_bounds__(256) void qkv_gemm(const float* __restrict__ bias) {
    int z = blockIdx.z;
    const __half* A  = g_inh + (size_t)z * B_ * S_ * E_;
    const __half* Wz = g_wh + (size_t)z * E_ * E_;
    const float*  bz = bias + z * E_;

    __shared__ unsigned As[128][20];
    __shared__ unsigned Ws[64][20];
    int t = threadIdx.x, w = t >> 5, lane = t & 31, g = lane >> 2, tig = lane & 3;
    int wm = (w & 3) * 32, wn = (w >> 2) * 32;
    int m0 = blockIdx.y * 128, n0 = blockIdx.x * 64;

    float acc[2][4][4] = {};
    int ar = t >> 3, ac2 = (t & 7) * 2;
    int wr = t >> 2, wc2 = (t & 3) * 4;

    for (int k0 = 0; k0 < E_; k0 += 32) {
        #pragma unroll
        for (int p = 0; p < 4; p++) {
            uint2 v = *(const uint2*)(A + (size_t)(m0 + ar + p*32) * E_ + k0 + ac2*2);
            As[ar + p*32][ac2] = v.x; As[ar + p*32][ac2+1] = v.y;
        }
        {
            uint4 v = *(const uint4*)(Wz + (size_t)(n0 + wr) * E_ + k0 + wc2*2);
            Ws[wr][wc2] = v.x; Ws[wr][wc2+1] = v.y; Ws[wr][wc2+2] = v.z; Ws[wr][wc2+3] = v.w;
        }
        __syncthreads();
        #pragma unroll
        for (int ks = 0; ks < 2; ks++) {
            int kp = ks*8 + tig;
            unsigned a[2][4], bf[4][2];
            #pragma unroll
            for (int mt = 0; mt < 2; mt++) {
                int r = wm + mt*16 + g;
                a[mt][0] = As[r  ][kp];   a[mt][1] = As[r+8][kp];
                a[mt][2] = As[r  ][kp+4]; a[mt][3] = As[r+8][kp+4];
            }
            #pragma unroll
            for (int nt = 0; nt < 4; nt++) {
                int n = wn + nt*8 + g;
                bf[nt][0] = Ws[n][kp]; bf[nt][1] = Ws[n][kp+4];
            }
            #pragma unroll
            for (int mt = 0; mt < 2; mt++)
                #pragma unroll
                for (int nt = 0; nt < 4; nt++)
                    mma_f16(acc[mt][nt], a[mt], bf[nt]);
        }
        __syncthreads();
    }
    #pragma unroll
    for (int mt = 0; mt < 2; mt++) {
        int m_ = m0 + wm + mt*16 + g;
        int bb = m_ >> 10, s0 = m_ & 1023;
        #pragma unroll
        for (int nt = 0; nt < 4; nt++) {
            int n_ = n0 + wn + nt*8 + tig*2;
            int h = n_ >> 6, d = n_ & 63;
            float bx = bz[n_], by = bz[n_+1];
            if (z == 2) {       // V transposed: [bh, d, s]
                size_t base = ((size_t)(bb*H_ + h)*D_);
                g_vh[(base + d  )*S_ + s0    ] = __float2half_rn(acc[mt][nt][0] + bx);
                g_vh[(base + d+1)*S_ + s0    ] = __float2half_rn(acc[mt][nt][1] + by);
                g_vh[(base + d  )*S_ + s0 + 8] = __float2half_rn(acc[mt][nt][2] + bx);
                g_vh[(base + d+1)*S_ + s0 + 8] = __float2half_rn(acc[mt][nt][3] + by);
            } else {
                __half* outp = (z == 0) ? g_qh : g_kh;
                size_t base = ((size_t)(bb*H_ + h)*S_);
                *(__half2*)&outp[(base + s0    )*D_ + d] =
                    __floats2half2_rn(acc[mt][nt][0] + bx, acc[mt][nt][1] + by);
                *(__half2*)&outp[(base + s0 + 8)*D_ + d] =
                    __floats2half2_rn(acc[mt][nt][2] + bx, acc[mt][nt][3] + by);
            }
        }
    }
}

// ---------------- K2: fused flash attention (fp16 mma), 4 warps -------------
// Spills each unnormalized P tile (half) + per-tile row max for attnmean.
__global__ __launch_bounds__(128) void flash_kernel() {
    int bh = blockIdx.y; int b = bh >> 4, h = bh & 15;
    int m0 = blockIdx.x * 64;
    const __half* Q  = g_qh + (size_t)bh * S_ * D_;
    const __half* Kp = g_kh + (size_t)bh * S_ * D_;
    const __half* Vp = g_vh + (size_t)bh * D_ * S_;   // [d][s]
    const float* mb = g_maskbias + b * S_;

    __shared__ unsigned Ks[64][36];   // K tile; reused as P tile
    __shared__ unsigned Vt[64][36];   // V [d][s-pair]

    int t = threadIdx.x, w = t >> 5, lane = t & 31, g = lane >> 2, tig = lane & 3;
    int wm = w * 16;
    int r_lo = m0 + wm + g, r_hi = r_lo + 8;

    {   // stage Q through Ks, hoist A-fragments
        int r = t >> 1, c0 = (t & 1) * 32;
        #pragma unroll
        for (int j = 0; j < 4; j++) {
            uint4 v = *(const uint4*)(Q + (size_t)(m0 + r) * D_ + c0 + j*8);
            int cc = c0/2 + j*4;
            Ks[r][cc] = v.x; Ks[r][cc+1] = v.y; Ks[r][cc+2] = v.z; Ks[r][cc+3] = v.w;
        }
    }
    __syncthreads();
    unsigned aq[4][4];
    #pragma unroll
    for (int ks = 0; ks < 4; ks++) {
        int kp = ks*8 + tig;
        aq[ks][0] = Ks[wm+g  ][kp];   aq[ks][1] = Ks[wm+g+8][kp];
        aq[ks][2] = Ks[wm+g  ][kp+4]; aq[ks][3] = Ks[wm+g+8][kp+4];
    }

    float acc[8][4] = {};
    float mlo = -1e30f, mhi = -1e30f, llo = 0.0f, lhi = 0.0f;

    for (int kt = 0; kt < 16; kt++) {
        __syncthreads();        // prior readers of Ks/Vt done
        {
            int r = t >> 1, c0 = (t & 1) * 32;
            #pragma unroll
            for (int j = 0; j < 4; j++) {
                int cc = c0/2 + j*4;
                uint4 kv = *(const uint4*)(Kp + (size_t)(kt*64 + r) * D_ + c0 + j*8);
                Ks[r][cc] = kv.x; Ks[r][cc+1] = kv.y; Ks[r][cc+2] = kv.z; Ks[r][cc+3] = kv.w;
                uint4 vv = *(const uint4*)(Vp + (size_t)r * S_ + kt*64 + c0 + j*8);
                Vt[r][cc] = vv.x; Vt[r][cc+1] = vv.y; Vt[r][cc+2] = vv.z; Vt[r][cc+3] = vv.w;
            }
        }
        __syncthreads();

        // S(16x64 per warp) = Q . K^T
        float s[8][4] = {};
        #pragma unroll
        for (int ks = 0; ks < 4; ks++) {
            int kp = ks*8 + tig;
            #pragma unroll
            for (int nt = 0; nt < 8; nt++) {
                unsigned bf[2] = { Ks[nt*8+g][kp], Ks[nt*8+g][kp+4] };
                mma_f16(s[nt], aq[ks], bf);
            }
        }

        // scale + rel bias + mask, online softmax over 64 cols
        float rml = -1e30f, rmh = -1e30f;
        #pragma unroll
        for (int nt = 0; nt < 8; nt++) {
            int c = kt*64 + nt*8 + tig*2;
            float mb0 = mb[c], mb1 = mb[c+1];
            s[nt][0] = s[nt][0]*0.125f + (float)(r_lo - c    ) + mb0;
            s[nt][1] = s[nt][1]*0.125f + (float)(r_lo - c - 1) + mb1;
            s[nt][2] = s[nt][2]*0.125f + (float)(r_hi - c    ) + mb0;
            s[nt][3] = s[nt][3]*0.125f + (float)(r_hi - c - 1) + mb1;
            rml = fmaxf(rml, fmaxf(s[nt][0], s[nt][1]));
            rmh = fmaxf(rmh, fmaxf(s[nt][2], s[nt][3]));
        }
        rml = fmaxf(rml, __shfl_xor_sync(0xffffffffu, rml, 1));
        rml = fmaxf(rml, __shfl_xor_sync(0xffffffffu, rml, 2));
        rmh = fmaxf(rmh, __shfl_xor_sync(0xffffffffu, rmh, 1));
        rmh = fmaxf(rmh, __shfl_xor_sync(0xffffffffu, rmh, 2));

        float mnl = fmaxf(mlo, rml), mnh = fmaxf(mhi, rmh);
        float sfl = __expf(mlo - mnl), sfh = __expf(mhi - mnh);
        float rsl = 0.0f, rsh = 0.0f;
        #pragma unroll
        for (int nt = 0; nt < 8; nt++) {
            s[nt][0] = __expf(s[nt][0] - mnl); s[nt][1] = __expf(s[nt][1] - mnl);
            s[nt][2] = __expf(s[nt][2] - mnh); s[nt][3] = __expf(s[nt][3] - mnh);
            rsl += s[nt][0] + s[nt][1]; rsh += s[nt][2] + s[nt][3];
        }
        rsl += __shfl_xor_sync(0xffffffffu, rsl, 1);
        rsl += __shfl_xor_sync(0xffffffffu, rsl, 2);
        rsh += __shfl_xor_sync(0xffffffffu, rsh, 1);
        rsh += __shfl_xor_sync(0xffffffffu, rsh, 2);
        llo = llo*sfl + rsl; lhi = lhi*sfh + rsh;
        mlo = mnl; mhi = mnh;
        #pragma unroll
        for (int nt = 0; nt < 8; nt++) {
            acc[nt][0] *= sfl; acc[nt][1] *= sfl;
            acc[nt][2] *= sfh; acc[nt][3] *= sfh;
        }

        __syncthreads();        // Ks readers done -> overwrite with P
        #pragma unroll
        for (int nt = 0; nt < 8; nt++) {
            Ks[wm+g  ][nt*4 + tig] = h2(s[nt][0], s[nt][1]);
            Ks[wm+g+8][nt*4 + tig] = h2(s[nt][2], s[nt][3]);
        }
        // per-tile row max for attnmean rescale
        if (tig == 0) {
            g_mt[((size_t)bh*16 + kt)*S_ + r_lo] = mlo;
            g_mt[((size_t)bh*16 + kt)*S_ + r_hi] = mhi;
        }
        __syncwarp();           // P rows are warp-local for the mma

        // acc(16x64) += P(16x64) . V(64x64)
        #pragma unroll
        for (int ks = 0; ks < 4; ks++) {
            int kp = ks*8 + tig;
            unsigned a[4] = { Ks[wm+g][kp], Ks[wm+g+8][kp],
                              Ks[wm+g][kp+4], Ks[wm+g+8][kp+4] };
            #pragma unroll
            for (int nt = 0; nt < 8; nt++) {
                unsigned bf[2] = { Vt[nt*8+g][kp], Vt[nt*8+g][kp+4] };
                mma_f16(acc[nt], a, bf);
            }
        }

        __syncthreads();        // all warps' P tiles visible in smem
        {   // coalesced spill: Ks word w = cols (2w, 2w+1) -> linear
            int r = t >> 1, cw = (t & 1) * 16;     // 16 words = 32 cols per thread
            __half* dst = &g_ph[((size_t)bh*S_ + m0 + r)*S_ + kt*64 + cw*2];
            #pragma unroll
            for (int j = 0; j < 4; j++)
                *(uint4*)(dst + j*8) = *(const uint4*)&Ks[r][cw + j*4];
        }
    }

    float il = 1.0f / llo, ih = 1.0f / lhi;
    __half* clo = &g_ctxh[((size_t)(b*S_ + r_lo))*E_ + h*D_];
    __half* chi = &g_ctxh[((size_t)(b*S_ + r_hi))*E_ + h*D_];
    #pragma unroll
    for (int nt = 0; nt < 8; nt++) {
        int d = nt*8 + tig*2;
        *(__half2*)&clo[d] = __floats2half2_rn(acc[nt][0]*il, acc[nt][1]*il);
        *(__half2*)&chi[d] = __floats2half2_rn(acc[nt][2]*ih, acc[nt][3]*ih);
    }
    if (tig == 0) {
        g_m[(size_t)bh*S_ + r_lo] = mlo; g_l[(size_t)bh*S_ + r_lo] = llo;
        g_m[(size_t)bh*S_ + r_hi] = mhi; g_l[(size_t)bh*S_ + r_hi] = lhi;
    }
}

// ---------------- K3: attn mean = streamed rescale of spilled P -------------
// block = one (b,q) row; out[c] = (1/16) sum_h p[b,h,q,c] * exp(mt-m)/l
__global__ __launch_bounds__(256) void attnmean_kernel(float* __restrict__ out_attn) {
    int bq = blockIdx.x;
    int b = bq >> 10, q = bq & 1023;
    __shared__ float sf[16][16];    // [h][kt]
    int t = threadIdx.x;
    {
        int h = t >> 4, kt = t & 15;
        int bh = b*H_ + h;
        sf[h][kt] = __expf(g_mt[((size_t)bh*16 + kt)*S_ + q] - g_m[(size_t)bh*S_ + q])
                    / g_l[(size_t)bh*S_ + q];
    }
    __syncthreads();

    int c0 = t * 4;
    int ktc = c0 >> 6;
    float a0 = 0.f, a1 = 0.f, a2 = 0.f, a3 = 0.f;
    #pragma unroll
    for (int h = 0; h < H_; h++) {
        const __half* p = g_ph + ((size_t)(b*H_ + h)*S_ + q)*S_ + c0;
        uint2 v = *(const uint2*)p;
        __half2 p01 = *reinterpret_cast<__half2*>(&v.x);
        __half2 p23 = *reinterpret_cast<__half2*>(&v.y);
        float s = sf[h][ktc];
        float2 f01 = __half22float2(p01), f23 = __half22float2(p23);
        a0 += f01.x * s; a1 += f01.y * s; a2 += f23.x * s; a3 += f23.y * s;
    }
    *(float4*)&out_attn[(size_t)bq * S_ + c0] =
        make_float4(a0*0.0625f, a1*0.0625f, a2*0.0625f, a3*0.0625f);
}

// ---------------- K4: out = ctx @ Wo^T + bo (fp16 mma, half in) -------------
__global__ __launch_bounds__(256) void out_gemm(
    const float* __restrict__ bias, float* __restrict__ out)
{
    __shared__ unsigned As[128][20];
    __shared__ unsigned Ws[64][20];
    int t = threadIdx.x, w = t >> 5, lane = t & 31, g = lane >> 2, tig = lane & 3;
    int wm = (w & 3) * 32, wn = (w >> 2) * 32;
    int m0 = blockIdx.y * 128, n0 = blockIdx.x * 64;

    float acc[2][4][4] = {};
    int ar = t >> 3, ac2 = (t & 7) * 2;
    int wr = t >> 2, wc2 = (t & 3) * 4;

    for (int k0 = 0; k0 < E_; k0 += 32) {
        #pragma unroll
        for (int p = 0; p < 4; p++) {
            uint2 v = *(const uint2*)(g_ctxh + (size_t)(m0 + ar + p*32) * E_ + k0 + ac2*2);
            As[ar + p*32][ac2] = v.x; As[ar + p*32][ac2+1] = v.y;
        }
        {
            uint4 v = *(const uint4*)(g_woh + (size_t)(n0 + wr) * E_ + k0 + wc2*2);
            Ws[wr][wc2] = v.x; Ws[wr][wc2+1] = v.y; Ws[wr][wc2+2] = v.z; Ws[wr][wc2+3] = v.w;
        }
        __syncthreads();
        #pragma unroll
        for (int ks = 0; ks < 2; ks++) {
            int kp = ks*8 + tig;
            unsigned a[2][4], bf[4][2];
            #pragma unroll
            for (int mt = 0; mt < 2; mt++) {
                int r = wm + mt*16 + g;
                a[mt][0] = As[r  ][kp];   a[mt][1] = As[r+8][kp];
                a[mt][2] = As[r  ][kp+4]; a[mt][3] = As[r+8][kp+4];
            }
            #pragma unroll
            for (int nt = 0; nt < 4; nt++) {
                int n = wn + nt*8 + g;
                bf[nt][0] = Ws[n][kp]; bf[nt][1] = Ws[n][kp+4];
            }
            #pragma unroll
            for (int mt = 0; mt < 2; mt++)
                #pragma unroll
                for (int nt = 0; nt < 4; nt++)
                    mma_f16(acc[mt][nt], a[mt], bf[nt]);
        }
        __syncthreads();
    }
    #pragma unroll
    for (int mt = 0; mt < 2; mt++) {
        int m_ = m0 + wm + mt*16 + g;
        #pragma unroll
        for (int nt = 0; nt < 4; nt++) {
            int n_ = n0 + wn + nt*8 + tig*2;
            float bx = bias[n_], by = bias[n_+1];
            *(float2*)&out[(size_t)m_ * E_ + n_] =
                make_float2(acc[mt][nt][0] + bx, acc[mt][nt][1] + by);
            *(float2*)&out[(size_t)(m_+8) * E_ + n_] =
                make_float2(acc[mt][nt][2] + bx, acc[mt][nt][3] + by);
        }
    }
}

// ---------------- launch ----------------------------------------------------
extern "C" void kernel_launch(void* const* d_in, const int* in_sizes, int n_in,
                              void* d_out, int out_size)
{
    const float* query = (const float*)d_in[0];
    const float* key   = (const float*)d_in[1];
    const float* value = (const float*)d_in[2];
    const void*  mask  = d_in[3];
    const float* win   = (const float*)d_in[4];
    const float* bin   = (const float*)d_in[5];
    const float* wout  = (const float*)d_in[6];
    const float* bout  = (const float*)d_in[7];

    float* out      = (float*)d_out;                      // [4,1024,1024] output
    float* out_attn = out + (size_t)B_ * S_ * E_;         // [4,1024,1024] attn mean

    const int NIN = B_*S_*E_/4;
    __half* inh = nullptr; __half* wh = nullptr; __half* woh = nullptr;
    cudaGetSymbolAddress((void**)&inh, g_inh);
    cudaGetSymbolAddress((void**)&wh,  g_wh);
    cudaGetSymbolAddress((void**)&woh, g_woh);

    mask_kernel<<<1, 1024>>>(mask);
    f2h_kernel<<<(NIN+255)/256, 256>>>(query, inh, NIN);
    f2h_kernel<<<(NIN+255)/256, 256>>>(key,   inh + (size_t)B_*S_*E_, NIN);
    f2h_kernel<<<(NIN+255)/256, 256>>>(value, inh + (size_t)2*B_*S_*E_, NIN);
    f2h_kernel<<<(3*E_*E_/4+255)/256, 256>>>(win,  wh,  3*E_*E_/4);
    f2h_kernel<<<(E_*E_/4+255)/256, 256>>>(wout, woh, E_*E_/4);
    qkv_gemm<<<dim3(16, 32, 3), 256>>>(bin);
    flash_kernel<<<dim3(16, 64), 128>>>();
    attnmean_kernel<<<B_*S_, 256>>>(out_attn);
    out_gemm<<<dim3(16, 32), 256>>>(bout, out);
}

// round 11
// speedup vs baseline: 2.1179x; 1.0552x over previous
#include <cuda_runtime.h>
#include <cuda_fp16.h>
#include <math.h>

#define B_ 4
#define S_ 1024
#define E_ 1024
#define H_ 16
#define D_ 64

// ---------------- scratch (alloc-free: __device__ globals, ~196 MB) --------
__device__ __align__(16) __half g_inh[3*B_*S_*E_];   // 24 MB pre-converted q/k/v inputs
__device__ __align__(16) __half g_wh[3*E_*E_];       // 6 MB  in_proj weights (half)
__device__ __align__(16) __half g_woh[E_*E_];        // 2 MB  out_proj weights (half)
__device__ __align__(16) __half g_qh[B_*H_*S_*D_];   // 8 MB  [b,h,s,d]
__device__ __align__(16) __half g_kh[B_*H_*S_*D_];   // 8 MB  [b,h,s,d]
__device__ __align__(16) __half g_vh[B_*H_*S_*D_];   // 8 MB  [b,h,d,s]  (transposed!)
__device__ __align__(16) __half g_ctxh[B_*S_*E_];    // 8 MB  [b,s,h*D+d]
__device__ __align__(16) __half g_ph[(size_t)B_*H_*S_*S_];  // 128 MB unnormalized P tiles
__device__ float g_mt[B_*H_*16*S_];                  // 4 MB  per-tile row max [bh,kt,q]
__device__ float g_m[B_*H_*S_];
__device__ float g_l[B_*H_*S_];
__device__ float g_maskbias[B_*S_];

// ---------------- fp16 helpers ----------------
__device__ __forceinline__ unsigned h2(float a, float b) {
    __half2 h = __floats2half2_rn(a, b);
    return *reinterpret_cast<unsigned*>(&h);
}

// D += A(16x16, row) * B(16x8, col); c[4] fp32, a[4]/b[2] = half2 regs
__device__ __forceinline__ void mma_f16(float* c, const unsigned* a, const unsigned* b) {
    asm volatile(
        "mma.sync.aligned.m16n8k16.row.col.f32.f16.f16.f32 "
        "{%0,%1,%2,%3}, {%4,%5,%6,%7}, {%8,%9}, {%0,%1,%2,%3};"
        : "+f"(c[0]), "+f"(c[1]), "+f"(c[2]), "+f"(c[3])
        : "r"(a[0]), "r"(a[1]), "r"(a[2]), "r"(a[3]), "r"(b[0]), "r"(b[1]));
}

// ---------------- K0a: fp32 -> fp16 bulk convert ----------------------------
__global__ void f2h_kernel(const float* __restrict__ in, __half* __restrict__ out, int n4) {
    int i = blockIdx.x * blockDim.x + threadIdx.x;
    if (i < n4) {
        float4 v = ((const float4*)in)[i];
        *(__half2*)(out + (size_t)i*4)     = __floats2half2_rn(v.x, v.y);
        *(__half2*)(out + (size_t)i*4 + 2) = __floats2half2_rn(v.z, v.w);
    }
}

// ---------------- K0b: mask dtype detection + expansion ----------------------
__global__ void mask_kernel(const void* __restrict__ mask_raw) {
    __shared__ int s_int, s_flt;
    int t = threadIdx.x;
    if (t == 0) { s_int = 1; s_flt = 1; }
    __syncthreads();
    const unsigned int* w = (const unsigned int*)mask_raw;
    unsigned int v = w[t];
    if (!(v == 0u || v == 1u))           atomicAnd(&s_int, 0);
    if (!(v == 0u || v == 0x3f800000u))  atomicAnd(&s_flt, 0);
    __syncthreads();
    int mode = s_int ? 0 : (s_flt ? 1 : 2);
    for (int i = t; i < B_*S_; i += 1024) {
        bool keep;
        if (mode == 0)      keep = ((const int*)mask_raw)[i] != 0;
        else if (mode == 1) keep = ((const float*)mask_raw)[i] != 0.0f;
        else                keep = ((const unsigned char*)mask_raw)[i] != 0;
        g_maskbias[i] = keep ? 0.0f : -INFINITY;
    }
}

// ---------------- K1: QKV projection (fp16 mma, half in/out) ----------------
__global__ __launch_bounds__(256) void qkv_gemm(const float* __restrict__ bias) {
    int z = blockIdx.z;
    const __half* A  = g_inh + (size_t)z * B_ * S_ * E_;
    const __half* Wz = g_wh + (size_t)z * E_ * E_;
    const float*  bz = bias + z * E_;

    __shared__ unsigned As[128][20];
    __shared__ unsigned Ws[64][20];
    int t = threadIdx.x, w = t >> 5, lane = t & 31, g = lane >> 2, tig = lane & 3;
    int wm = (w & 3) * 32, wn = (w >> 2) * 32;
    int m0 = blockIdx.y * 128, n0 = blockIdx.x * 64;

    float acc[2][4][4] = {};
    int ar = t >> 3, ac2 = (t & 7) * 2;
    int wr = t >> 2, wc2 = (t & 3) * 4;

    for (int k0 = 0; k0 < E_; k0 += 32) {
        #pragma unroll
        for (int p = 0; p < 4; p++) {
            uint2 v = *(const uint2*)(A + (size_t)(m0 + ar + p*32) * E_ + k0 + ac2*2);
            As[ar + p*32][ac2] = v.x; As[ar + p*32][ac2+1] = v.y;
        }
        {
            uint4 v = *(const uint4*)(Wz + (size_t)(n0 + wr) * E_ + k0 + wc2*2);
            Ws[wr][wc2] = v.x; Ws[wr][wc2+1] = v.y; Ws[wr][wc2+2] = v.z; Ws[wr][wc2+3] = v.w;
        }
        __syncthreads();
        #pragma unroll
        for (int ks = 0; ks < 2; ks++) {
            int kp = ks*8 + tig;
            unsigned a[2][4], bf[4][2];
            #pragma unroll
            for (int mt = 0; mt < 2; mt++) {
                int r = wm + mt*16 + g;
                a[mt][0] = As[r  ][kp];   a[mt][1] = As[r+8][kp];
                a[mt][2] = As[r  ][kp+4]; a[mt][3] = As[r+8][kp+4];
            }
            #pragma unroll
            for (int nt = 0; nt < 4; nt++) {
                int n = wn + nt*8 + g;
                bf[nt][0] = Ws[n][kp]; bf[nt][1] = Ws[n][kp+4];
            }
            #pragma unroll
            for (int mt = 0; mt < 2; mt++)
                #pragma unroll
                for (int nt = 0; nt < 4; nt++)
                    mma_f16(acc[mt][nt], a[mt], bf[nt]);
        }
        __syncthreads();
    }
    #pragma unroll
    for (int mt = 0; mt < 2; mt++) {
        int m_ = m0 + wm + mt*16 + g;
        int bb = m_ >> 10, s0 = m_ & 1023;
        #pragma unroll
        for (int nt = 0; nt < 4; nt++) {
            int n_ = n0 + wn + nt*8 + tig*2;
            int h = n_ >> 6, d = n_ & 63;
            float bx = bz[n_], by = bz[n_+1];
            if (z == 2) {       // V transposed: [bh, d, s]
                size_t base = ((size_t)(bb*H_ + h)*D_);
                g_vh[(base + d  )*S_ + s0    ] = __float2half_rn(acc[mt][nt][0] + bx);
                g_vh[(base + d+1)*S_ + s0    ] = __float2half_rn(acc[mt][nt][1] + by);
                g_vh[(base + d  )*S_ + s0 + 8] = __float2half_rn(acc[mt][nt][2] + bx);
                g_vh[(base + d+1)*S_ + s0 + 8] = __float2half_rn(acc[mt][nt][3] + by);
            } else {
                __half* outp = (z == 0) ? g_qh : g_kh;
                size_t base = ((size_t)(bb*H_ + h)*S_);
                *(__half2*)&outp[(base + s0    )*D_ + d] =
                    __floats2half2_rn(acc[mt][nt][0] + bx, acc[mt][nt][1] + by);
                *(__half2*)&outp[(base + s0 + 8)*D_ + d] =
                    __floats2half2_rn(acc[mt][nt][2] + bx, acc[mt][nt][3] + by);
            }
        }
    }
}

// ---------------- K2: fused flash attention (fp16 mma), 8 warps, q-tile 128 -
// Dedicated Ps buffer (2 block-syncs/iter); coalesced row-contiguous P spill.
__global__ __launch_bounds__(256) void flash_kernel() {
    int bh = blockIdx.y; int b = bh >> 4, h = bh & 15;
    int m0 = blockIdx.x * 128;
    const __half* Q  = g_qh + (size_t)bh * S_ * D_;
    const __half* Kp = g_kh + (size_t)bh * S_ * D_;
    const __half* Vp = g_vh + (size_t)bh * D_ * S_;   // [d][s]
    const float* mb = g_maskbias + b * S_;

    __shared__ unsigned Ks[64][36];    // K tile [key][k-pair]
    __shared__ unsigned Vt[64][36];    // V [d][s-pair]
    __shared__ unsigned Ps[128][36];   // Q staging, then P tiles (warp-local rows)

    int t = threadIdx.x, w = t >> 5, lane = t & 31, g = lane >> 2, tig = lane & 3;
    int wm = w * 16;
    int r_lo = m0 + wm + g, r_hi = r_lo + 8;

    {   // stage Q tile (128 rows) through Ps, hoist A-fragments
        int r = t >> 1, c0 = (t & 1) * 32;
        #pragma unroll
        for (int j = 0; j < 4; j++) {
            uint4 v = *(const uint4*)(Q + (size_t)(m0 + r) * D_ + c0 + j*8);
            int cc = c0/2 + j*4;
            Ps[r][cc] = v.x; Ps[r][cc+1] = v.y; Ps[r][cc+2] = v.z; Ps[r][cc+3] = v.w;
        }
    }
    __syncthreads();
    unsigned aq[4][4];
    #pragma unroll
    for (int ks = 0; ks < 4; ks++) {
        int kp = ks*8 + tig;
        aq[ks][0] = Ps[wm+g  ][kp];   aq[ks][1] = Ps[wm+g+8][kp];
        aq[ks][2] = Ps[wm+g  ][kp+4]; aq[ks][3] = Ps[wm+g+8][kp+4];
    }

    float acc[8][4] = {};
    float mlo = -1e30f, mhi = -1e30f, llo = 0.0f, lhi = 0.0f;

    for (int kt = 0; kt < 16; kt++) {
        __syncthreads();        // prior S-mma/PV-mma readers of Ks/Vt done (aq, iter 0)
        {   // K,V tiles 64x64: 256 threads, 4 threads/row, 2 uint4 each
            int r = t >> 2, ch = (t & 3) * 16;     // half offset within row
            int cw = ch >> 1;                       // word offset
            uint4 kv0 = *(const uint4*)(Kp + (size_t)(kt*64 + r) * D_ + ch);
            uint4 kv1 = *(const uint4*)(Kp + (size_t)(kt*64 + r) * D_ + ch + 8);
            *(uint4*)&Ks[r][cw] = kv0; *(uint4*)&Ks[r][cw+4] = kv1;
            uint4 vv0 = *(const uint4*)(Vp + (size_t)r * S_ + kt*64 + ch);
            uint4 vv1 = *(const uint4*)(Vp + (size_t)r * S_ + kt*64 + ch + 8);
            *(uint4*)&Vt[r][cw] = vv0; *(uint4*)&Vt[r][cw+4] = vv1;
        }
        __syncthreads();

        // S(16x64 per warp) = Q . K^T
        float s[8][4] = {};
        #pragma unroll
        for (int ks = 0; ks < 4; ks++) {
            int kp = ks*8 + tig;
            #pragma unroll
            for (int nt = 0; nt < 8; nt++) {
                unsigned bf[2] = { Ks[nt*8+g][kp], Ks[nt*8+g][kp+4] };
                mma_f16(s[nt], aq[ks], bf);
            }
        }

        // scale + rel bias + mask, online softmax over 64 cols
        float rml = -1e30f, rmh = -1e30f;
        #pragma unroll
        for (int nt = 0; nt < 8; nt++) {
            int c = kt*64 + nt*8 + tig*2;
            float mb0 = mb[c], mb1 = mb[c+1];
            s[nt][0] = s[nt][0]*0.125f + (float)(r_lo - c    ) + mb0;
            s[nt][1] = s[nt][1]*0.125f + (float)(r_lo - c - 1) + mb1;
            s[nt][2] = s[nt][2]*0.125f + (float)(r_hi - c    ) + mb0;
            s[nt][3] = s[nt][3]*0.125f + (float)(r_hi - c - 1) + mb1;
            rml = fmaxf(rml, fmaxf(s[nt][0], s[nt][1]));
            rmh = fmaxf(rmh, fmaxf(s[nt][2], s[nt][3]));
        }
        rml = fmaxf(rml, __shfl_xor_sync(0xffffffffu, rml, 1));
        rml = fmaxf(rml, __shfl_xor_sync(0xffffffffu, rml, 2));
        rmh = fmaxf(rmh, __shfl_xor_sync(0xffffffffu, rmh, 1));
        rmh = fmaxf(rmh, __shfl_xor_sync(0xffffffffu, rmh, 2));

        float mnl = fmaxf(mlo, rml), mnh = fmaxf(mhi, rmh);
        float sfl = __expf(mlo - mnl), sfh = __expf(mhi - mnh);
        float rsl = 0.0f, rsh = 0.0f;
        #pragma unroll
        for (int nt = 0; nt < 8; nt++) {
            s[nt][0] = __expf(s[nt][0] - mnl); s[nt][1] = __expf(s[nt][1] - mnl);
            s[nt][2] = __expf(s[nt][2] - mnh); s[nt][3] = __expf(s[nt][3] - mnh);
            rsl += s[nt][0] + s[nt][1]; rsh += s[nt][2] + s[nt][3];
        }
        rsl += __shfl_xor_sync(0xffffffffu, rsl, 1);
        rsl += __shfl_xor_sync(0xffffffffu, rsl, 2);
        rsh += __shfl_xor_sync(0xffffffffu, rsh, 1);
        rsh += __shfl_xor_sync(0xffffffffu, rsh, 2);
        llo = llo*sfl + rsl; lhi = lhi*sfh + rsh;
        mlo = mnl; mhi = mnh;
        #pragma unroll
        for (int nt = 0; nt < 8; nt++) {
            acc[nt][0] *= sfl; acc[nt][1] *= sfl;
            acc[nt][2] *= sfh; acc[nt][3] *= sfh;
        }

        // write P rows (warp-local) into Ps
        #pragma unroll
        for (int nt = 0; nt < 8; nt++) {
            Ps[wm+g  ][nt*4 + tig] = h2(s[nt][0], s[nt][1]);
            Ps[wm+g+8][nt*4 + tig] = h2(s[nt][2], s[nt][3]);
        }
        if (tig == 0) {
            g_mt[((size_t)bh*16 + kt)*S_ + r_lo] = mlo;
            g_mt[((size_t)bh*16 + kt)*S_ + r_hi] = mhi;
        }
        __syncwarp();           // P rows are warp-local

        // acc(16x64) += P(16x64) . V(64x64)
        #pragma unroll
        for (int ks = 0; ks < 4; ks++) {
            int kp = ks*8 + tig;
            unsigned a[4] = { Ps[wm+g][kp], Ps[wm+g+8][kp],
                              Ps[wm+g][kp+4], Ps[wm+g+8][kp+4] };
            #pragma unroll
            for (int nt = 0; nt < 8; nt++) {
                unsigned bf[2] = { Vt[nt*8+g][kp], Vt[nt*8+g][kp+4] };
                mma_f16(acc[nt], a, bf);
            }
        }

        // coalesced spill: quarter-warp per row (8 lanes x 16B = full 128B row)
        #pragma unroll
        for (int pass = 0; pass < 4; pass++) {
            int r = wm + pass*4 + (lane >> 3);
            int seg = lane & 7;
            *(uint4*)&g_ph[((size_t)bh*S_ + m0 + r)*S_ + kt*64 + seg*8] =
                *(const uint4*)&Ps[r][seg*4];
        }
    }

    float il = 1.0f / llo, ih = 1.0f / lhi;
    __half* clo = &g_ctxh[((size_t)(b*S_ + r_lo))*E_ + h*D_];
    __half* chi = &g_ctxh[((size_t)(b*S_ + r_hi))*E_ + h*D_];
    #pragma unroll
    for (int nt = 0; nt < 8; nt++) {
        int d = nt*8 + tig*2;
        *(__half2*)&clo[d] = __floats2half2_rn(acc[nt][0]*il, acc[nt][1]*il);
        *(__half2*)&chi[d] = __floats2half2_rn(acc[nt][2]*ih, acc[nt][3]*ih);
    }
    if (tig == 0) {
        g_m[(size_t)bh*S_ + r_lo] = mlo; g_l[(size_t)bh*S_ + r_lo] = llo;
        g_m[(size_t)bh*S_ + r_hi] = mhi; g_l[(size_t)bh*S_ + r_hi] = lhi;
    }
}

// ---------------- K3: attn mean = streamed rescale of spilled P -------------
__global__ __launch_bounds__(256) void attnmean_kernel(float* __restrict__ out_attn) {
    int bq = blockIdx.x;
    int b = bq >> 10, q = bq & 1023;
    __shared__ float sf[16][16];    // [h][kt]
    int t = threadIdx.x;
    {
        int h = t >> 4, kt = t & 15;
        int bh = b*H_ + h;
        sf[h][kt] = __expf(g_mt[((size_t)bh*16 + kt)*S_ + q] - g_m[(size_t)bh*S_ + q])
                    / g_l[(size_t)bh*S_ + q];
    }
    __syncthreads();

    int c0 = t * 4;
    int ktc = c0 >> 6;
    float a0 = 0.f, a1 = 0.f, a2 = 0.f, a3 = 0.f;
    #pragma unroll
    for (int h = 0; h < H_; h++) {
        const __half* p = g_ph + ((size_t)(b*H_ + h)*S_ + q)*S_ + c0;
        uint2 v = *(const uint2*)p;
        __half2 p01 = *reinterpret_cast<__half2*>(&v.x);
        __half2 p23 = *reinterpret_cast<__half2*>(&v.y);
        float s = sf[h][ktc];
        float2 f01 = __half22float2(p01), f23 = __half22float2(p23);
        a0 += f01.x * s; a1 += f01.y * s; a2 += f23.x * s; a3 += f23.y * s;
    }
    *(float4*)&out_attn[(size_t)bq * S_ + c0] =
        make_float4(a0*0.0625f, a1*0.0625f, a2*0.0625f, a3*0.0625f);
}

// ---------------- K4: out = ctx @ Wo^T + bo (fp16 mma, half in) -------------
__global__ __launch_bounds__(256) void out_gemm(
    const float* __restrict__ bias, float* __restrict__ out)
{
    __shared__ unsigned As[128][20];
    __shared__ unsigned Ws[64][20];
    int t = threadIdx.x, w = t >> 5, lane = t & 31, g = lane >> 2, tig = lane & 3;
    int wm = (w & 3) * 32, wn = (w >> 2) * 32;
    int m0 = blockIdx.y * 128, n0 = blockIdx.x * 64;

    float acc[2][4][4] = {};
    int ar = t >> 3, ac2 = (t & 7) * 2;
    int wr = t >> 2, wc2 = (t & 3) * 4;

    for (int k0 = 0; k0 < E_; k0 += 32) {
        #pragma unroll
        for (int p = 0; p < 4; p++) {
            uint2 v = *(const uint2*)(g_ctxh + (size_t)(m0 + ar + p*32) * E_ + k0 + ac2*2);
            As[ar + p*32][ac2] = v.x; As[ar + p*32][ac2+1] = v.y;
        }
        {
            uint4 v = *(const uint4*)(g_woh + (size_t)(n0 + wr) * E_ + k0 + wc2*2);
            Ws[wr][wc2] = v.x; Ws[wr][wc2+1] = v.y; Ws[wr][wc2+2] = v.z; Ws[wr][wc2+3] = v.w;
        }
        __syncthreads();
        #pragma unroll
        for (int ks = 0; ks < 2; ks++) {
            int kp = ks*8 + tig;
            unsigned a[2][4], bf[4][2];
            #pragma unroll
            for (int mt = 0; mt < 2; mt++) {
                int r = wm + mt*16 + g;
                a[mt][0] = As[r  ][kp];   a[mt][1] = As[r+8][kp];
                a[mt][2] = As[r  ][kp+4]; a[mt][3] = As[r+8][kp+4];
            }
            #pragma unroll
            for (int nt = 0; nt < 4; nt++) {
                int n = wn + nt*8 + g;
                bf[nt][0] = Ws[n][kp]; bf[nt][1] = Ws[n][kp+4];
            }
            #pragma unroll
            for (int mt = 0; mt < 2; mt++)
                #pragma unroll
                for (int nt = 0; nt < 4; nt++)
                    mma_f16(acc[mt][nt], a[mt], bf[nt]);
        }
        __syncthreads();
    }
    #pragma unroll
    for (int mt = 0; mt < 2; mt++) {
        int m_ = m0 + wm + mt*16 + g;
        #pragma unroll
        for (int nt = 0; nt < 4; nt++) {
            int n_ = n0 + wn + nt*8 + tig*2;
            float bx = bias[n_], by = bias[n_+1];
            *(float2*)&out[(size_t)m_ * E_ + n_] =
                make_float2(acc[mt][nt][0] + bx, acc[mt][nt][1] + by);
            *(float2*)&out[(size_t)(m_+8) * E_ + n_] =
                make_float2(acc[mt][nt][2] + bx, acc[mt][nt][3] + by);
        }
    }
}

// ---------------- launch ----------------------------------------------------
extern "C" void kernel_launch(void* const* d_in, const int* in_sizes, int n_in,
                              void* d_out, int out_size)
{
    const float* query = (const float*)d_in[0];
    const float* key   = (const float*)d_in[1];
    const float* value = (const float*)d_in[2];
    const void*  mask  = d_in[3];
    const float* win   = (const float*)d_in[4];
    const float* bin   = (const float*)d_in[5];
    const float* wout  = (const float*)d_in[6];
    const float* bout  = (const float*)d_in[7];

    float* out      = (float*)d_out;                      // [4,1024,1024] output
    float* out_attn = out + (size_t)B_ * S_ * E_;         // [4,1024,1024] attn mean

    const int NIN = B_*S_*E_/4;
    __half* inh = nullptr; __half* wh = nullptr; __half* woh = nullptr;
    cudaGetSymbolAddress((void**)&inh, g_inh);
    cudaGetSymbolAddress((void**)&wh,  g_wh);
    cudaGetSymbolAddress((void**)&woh, g_woh);

    mask_kernel<<<1, 1024>>>(mask);
    f2h_kernel<<<(NIN+255)/256, 256>>>(query, inh, NIN);
    f2h_kernel<<<(NIN+255)/256, 256>>>(key,   inh + (size_t)B_*S_*E_, NIN);
    f2h_kernel<<<(NIN+255)/256, 256>>>(value, inh + (size_t)2*B_*S_*E_, NIN);
    f2h_kernel<<<(3*E_*E_/4+255)/256, 256>>>(win,  wh,  3*E_*E_/4);
    f2h_kernel<<<(E_*E_/4+255)/256, 256>>>(wout, woh, E_*E_/4);
    qkv_gemm<<<dim3(16, 32, 3), 256>>>(bin);
    flash_kernel<<<dim3(8, 64), 256>>>();
    attnmean_kernel<<<B_*S_, 256>>>(out_attn);
    out_gemm<<<dim3(16, 32), 256>>>(bout, out);
}